// round 2
// baseline (speedup 1.0000x reference)
#include <cuda_runtime.h>
#include <math_constants.h>
#include <cstddef>

#define N_TOK 2048
#define BATCH 4
#define DM    1024
#define DKV   256          // KV_HEADS * D_HEAD
#define M_TOTAL (BATCH * N_TOK)   // 8192
#define AP 65              // padded row stride for attention smem tiles

// ---------------- scratch (device globals; no allocations allowed) ----------------
__device__ float g_WqS[256 * 1024];
__device__ float g_WkM[256 * 1024];
__device__ float g_WvM[256 * 1024];
__device__ float g_WoS[1024 * 256];
__device__ float g_bias[4095 * 4];
__device__ float g_Q[M_TOTAL * DKV];
__device__ float g_K[M_TOTAL * DKV];
__device__ float g_V[M_TOTAL * DKV];
__device__ float g_O[M_TOTAL * DKV];

// ---------------- fold weights + bias table ----------------
// WqS[h*64+d][col] = sum_g Wq[(g*4+h)*64+d][col]         (q summed over group)
// WkM/WvM          = 0.25 * sum_g (...)                  (k,v group-mean)
// WoS[j][c]        = sum_g Wo[j][g*256+c]                (tile-then-matmul collapsed)
// g_bias[rel+2047][h] = 0.25 * sum_g rel_bias[bucket(rel)][g*4+h]
__global__ void fold_kernel(const float* __restrict__ Wq, const float* __restrict__ Wk,
                            const float* __restrict__ Wv, const float* __restrict__ Wo,
                            const float* __restrict__ rb) {
    int idx = blockIdx.x * blockDim.x + threadIdx.x;
    if (idx < 256 * 1024) {
        int r   = idx >> 10;      // 0..255
        int col = idx & 1023;
        int h = r >> 6;           // 0..3
        int d = r & 63;
        float sq = 0.f, sk = 0.f, sv = 0.f;
        #pragma unroll
        for (int g = 0; g < 4; g++) {
            int src = ((g * 4 + h) * 64 + d) * 1024 + col;
            sq += Wq[src]; sk += Wk[src]; sv += Wv[src];
        }
        g_WqS[idx] = sq;
        g_WkM[idx] = sk * 0.25f;
        g_WvM[idx] = sv * 0.25f;

        int j = idx >> 8;         // 0..1023
        int c = idx & 255;
        float so = 0.f;
        #pragma unroll
        for (int g = 0; g < 4; g++) so += Wo[j * 1024 + g * 256 + c];
        g_WoS[idx] = so;
    }
    if (idx < 4095 * 4) {
        int i = idx >> 2;
        int h = idx & 3;
        int rel = i - 2047;                       // rel = s - n
        int bucket = (rel > 0) ? 16 : 0;
        int rp = rel < 0 ? -rel : rel;
        int lb;
        if (rp < 8) {
            lb = rp;
        } else {
            // integer thresholds of 8 + floor(8*log(rp/8)/log(16)); 16/32/64 are
            // exact in f32 (same mantissa as ln2 scaled by power of two)
            int cnt = (rp >= 12) + (rp >= 16) + (rp >= 23) + (rp >= 32) +
                      (rp >= 46) + (rp >= 64) + (rp >= 91);
            lb = 8 + cnt;                         // capped at 15 by construction
        }
        bucket += lb;
        float s = 0.f;
        #pragma unroll
        for (int g = 0; g < 4; g++) s += rb[bucket * 16 + g * 4 + h];
        g_bias[idx] = s * 0.25f;
    }
}

// ---------------- generic C[M,N] = A[M,K] * B[N,K]^T  (fp32, smem tiled) ----------------
// 64x64 tile, BK=16, 256 threads, 4x4 microtile per thread. M,N multiples of 64, K of 16.
__global__ void gemm_nt(const float* __restrict__ A, const float* __restrict__ B,
                        float* __restrict__ C, int M, int N, int K) {
    __shared__ float As[64][17];
    __shared__ float Bs[64][17];
    int tid = threadIdx.x;
    int tx = tid & 15, ty = tid >> 4;
    int m0 = blockIdx.y * 64, n0 = blockIdx.x * 64;
    int lrow = tid >> 2, lseg = (tid & 3) * 4;

    float acc[4][4] = {};
    for (int kt = 0; kt < K; kt += 16) {
        float4 a = *(const float4*)(A + (size_t)(m0 + lrow) * K + kt + lseg);
        float4 b = *(const float4*)(B + (size_t)(n0 + lrow) * K + kt + lseg);
        As[lrow][lseg + 0] = a.x; As[lrow][lseg + 1] = a.y;
        As[lrow][lseg + 2] = a.z; As[lrow][lseg + 3] = a.w;
        Bs[lrow][lseg + 0] = b.x; Bs[lrow][lseg + 1] = b.y;
        Bs[lrow][lseg + 2] = b.z; Bs[lrow][lseg + 3] = b.w;
        __syncthreads();
        #pragma unroll
        for (int k = 0; k < 16; k++) {
            float av[4], bv[4];
            #pragma unroll
            for (int i = 0; i < 4; i++) av[i] = As[ty * 4 + i][k];
            #pragma unroll
            for (int j = 0; j < 4; j++) bv[j] = Bs[tx * 4 + j][k];
            #pragma unroll
            for (int i = 0; i < 4; i++)
                #pragma unroll
                for (int j = 0; j < 4; j++) acc[i][j] += av[i] * bv[j];
        }
        __syncthreads();
    }
    #pragma unroll
    for (int i = 0; i < 4; i++)
        #pragma unroll
        for (int j = 0; j < 4; j++)
            C[(size_t)(m0 + ty * 4 + i) * N + n0 + tx * 4 + j] = acc[i][j];
}

// ---------------- flash attention: 4 heads, d=64, bias by relative position ----------------
// grid (32 q-tiles, 16 b*h), 256 threads, online softmax. Dynamic smem: 4 * 64*AP floats.
__global__ void attn_kernel() {
    extern __shared__ float sm[];
    float* Qs = sm;
    float* Ks = sm + 64 * AP;
    float* Vs = sm + 2 * 64 * AP;
    float* Ps = sm + 3 * 64 * AP;

    int tid = threadIdx.x;
    int tx = tid & 15, ty = tid >> 4;
    int q0 = blockIdx.x * 64;
    int bh = blockIdx.y;
    int b = bh >> 2, h = bh & 3;

    const float* Qg = g_Q + ((size_t)(b * N_TOK + q0)) * DKV + h * 64;
    #pragma unroll
    for (int p = 0; p < 4; p++) {
        int e = tid + p * 256;                 // 1024 float4 slots
        int row = e >> 4, seg = (e & 15) * 4;
        float4 v = *(const float4*)(Qg + (size_t)row * DKV + seg);
        Qs[row * AP + seg + 0] = v.x; Qs[row * AP + seg + 1] = v.y;
        Qs[row * AP + seg + 2] = v.z; Qs[row * AP + seg + 3] = v.w;
    }

    float m_i[4], l_i[4], acc[4][4];
    #pragma unroll
    for (int i = 0; i < 4; i++) {
        m_i[i] = -CUDART_INF_F; l_i[i] = 0.f;
        #pragma unroll
        for (int j = 0; j < 4; j++) acc[i][j] = 0.f;
    }
    __syncthreads();

    for (int kv0 = 0; kv0 < N_TOK; kv0 += 64) {
        const float* Kg = g_K + ((size_t)(b * N_TOK + kv0)) * DKV + h * 64;
        const float* Vg = g_V + ((size_t)(b * N_TOK + kv0)) * DKV + h * 64;
        #pragma unroll
        for (int p = 0; p < 4; p++) {
            int e = tid + p * 256;
            int row = e >> 4, seg = (e & 15) * 4;
            float4 kv = *(const float4*)(Kg + (size_t)row * DKV + seg);
            Ks[row * AP + seg + 0] = kv.x; Ks[row * AP + seg + 1] = kv.y;
            Ks[row * AP + seg + 2] = kv.z; Ks[row * AP + seg + 3] = kv.w;
            float4 vv = *(const float4*)(Vg + (size_t)row * DKV + seg);
            Vs[row * AP + seg + 0] = vv.x; Vs[row * AP + seg + 1] = vv.y;
            Vs[row * AP + seg + 2] = vv.z; Vs[row * AP + seg + 3] = vv.w;
        }
        __syncthreads();

        // S = Q K^T  (4x4 fragment per thread)
        float s[4][4] = {};
        #pragma unroll
        for (int d = 0; d < 64; d++) {
            float qv[4], kvv[4];
            #pragma unroll
            for (int i = 0; i < 4; i++) qv[i]  = Qs[(ty * 4 + i) * AP + d];
            #pragma unroll
            for (int j = 0; j < 4; j++) kvv[j] = Ks[(tx * 4 + j) * AP + d];
            #pragma unroll
            for (int i = 0; i < 4; i++)
                #pragma unroll
                for (int j = 0; j < 4; j++) s[i][j] += qv[i] * kvv[j];
        }
        // + relative-position bias
        #pragma unroll
        for (int i = 0; i < 4; i++)
            #pragma unroll
            for (int j = 0; j < 4; j++)
                s[i][j] += g_bias[((kv0 + tx * 4 + j) - (q0 + ty * 4 + i) + 2047) * 4 + h];

        // online softmax: row stats across the 16 lanes of a row-group (width-16 shuffles)
        float alpha[4];
        #pragma unroll
        for (int i = 0; i < 4; i++) {
            float mx = fmaxf(fmaxf(s[i][0], s[i][1]), fmaxf(s[i][2], s[i][3]));
            #pragma unroll
            for (int off = 8; off; off >>= 1)
                mx = fmaxf(mx, __shfl_xor_sync(0xffffffffu, mx, off, 16));
            float mnew = fmaxf(m_i[i], mx);
            alpha[i] = expf(m_i[i] - mnew);     // expf(-inf)=0 on first tile
            float ps = 0.f;
            #pragma unroll
            for (int j = 0; j < 4; j++) { s[i][j] = expf(s[i][j] - mnew); ps += s[i][j]; }
            #pragma unroll
            for (int off = 8; off; off >>= 1)
                ps += __shfl_xor_sync(0xffffffffu, ps, off, 16);
            l_i[i] = l_i[i] * alpha[i] + ps;
            m_i[i] = mnew;
        }
        // P to smem
        #pragma unroll
        for (int i = 0; i < 4; i++)
            #pragma unroll
            for (int j = 0; j < 4; j++)
                Ps[(ty * 4 + i) * AP + tx * 4 + j] = s[i][j];
        __syncthreads();

        // O = diag(alpha) O + P V   (thread owns rows ty*4.., d-cols tx*4..)
        #pragma unroll
        for (int i = 0; i < 4; i++)
            #pragma unroll
            for (int j = 0; j < 4; j++) acc[i][j] *= alpha[i];
        #pragma unroll 8
        for (int ss = 0; ss < 64; ss++) {
            float pv[4], vv[4];
            #pragma unroll
            for (int i = 0; i < 4; i++) pv[i] = Ps[(ty * 4 + i) * AP + ss];
            #pragma unroll
            for (int j = 0; j < 4; j++) vv[j] = Vs[ss * AP + tx * 4 + j];
            #pragma unroll
            for (int i = 0; i < 4; i++)
                #pragma unroll
                for (int j = 0; j < 4; j++) acc[i][j] += pv[i] * vv[j];
        }
        __syncthreads();
    }

    float* Og = g_O + ((size_t)(b * N_TOK + q0)) * DKV + h * 64;
    #pragma unroll
    for (int i = 0; i < 4; i++) {
        float inv = 1.f / l_i[i];
        #pragma unroll
        for (int j = 0; j < 4; j++)
            Og[(size_t)(ty * 4 + i) * DKV + tx * 4 + j] = acc[i][j] * inv;
    }
}

// ---------------- launch ----------------
extern "C" void kernel_launch(void* const* d_in, const int* in_sizes, int n_in,
                              void* d_out, int out_size) {
    const float* hs = (const float*)d_in[0];
    const float* Wq = (const float*)d_in[1];
    const float* Wk = (const float*)d_in[2];
    const float* Wv = (const float*)d_in[3];
    const float* Wo = (const float*)d_in[4];
    const float* rb = (const float*)d_in[5];
    float* out = (float*)d_out;

    void *pWqS, *pWkM, *pWvM, *pWoS, *pQ, *pK, *pV, *pO;
    cudaGetSymbolAddress(&pWqS, g_WqS);
    cudaGetSymbolAddress(&pWkM, g_WkM);
    cudaGetSymbolAddress(&pWvM, g_WvM);
    cudaGetSymbolAddress(&pWoS, g_WoS);
    cudaGetSymbolAddress(&pQ, g_Q);
    cudaGetSymbolAddress(&pK, g_K);
    cudaGetSymbolAddress(&pV, g_V);
    cudaGetSymbolAddress(&pO, g_O);

    fold_kernel<<<1024, 256>>>(Wq, Wk, Wv, Wo, rb);

    dim3 gProj(DKV / 64, M_TOTAL / 64);     // (4, 128)
    gemm_nt<<<gProj, 256>>>(hs, (const float*)pWqS, (float*)pQ, M_TOTAL, DKV, DM);
    gemm_nt<<<gProj, 256>>>(hs, (const float*)pWkM, (float*)pK, M_TOTAL, DKV, DM);
    gemm_nt<<<gProj, 256>>>(hs, (const float*)pWvM, (float*)pV, M_TOTAL, DKV, DM);

    int smem_bytes = 4 * 64 * AP * sizeof(float);   // 66560
    cudaFuncSetAttribute(attn_kernel, cudaFuncAttributeMaxDynamicSharedMemorySize, smem_bytes);
    attn_kernel<<<dim3(N_TOK / 64, BATCH * 4), 256, smem_bytes>>>();

    dim3 gOut(DM / 64, M_TOTAL / 64);       // (16, 128)
    gemm_nt<<<gOut, 256>>>((const float*)pO, (const float*)pWoS, out, M_TOTAL, DM, DKV);
}

// round 4
// speedup vs baseline: 1.2729x; 1.2729x over previous
#include <cuda_runtime.h>
#include <math_constants.h>
#include <cstddef>

#define N_TOK 2048
#define BATCH 4
#define DM    1024
#define DKV   256
#define M_TOTAL (BATCH * N_TOK)   // 8192
#define AP 65                     // attention smem row stride

#define BM 128
#define BN 64
#define BK 32
#define LDT 36                    // BK + 4 pad (keeps 16B align, conflict-free frags)

// ---------------- scratch ----------------
__device__ float g_Wf[768 * 1024];       // rows 0-255 WqS, 256-511 WkM, 512-767 WvM
__device__ float g_WoS[1024 * 256];
__device__ float g_bias[4095 * 4];
__device__ float g_Q[M_TOTAL * DKV];
__device__ float g_K[M_TOTAL * DKV];
__device__ float g_V[M_TOTAL * DKV];
__device__ float g_O[M_TOTAL * DKV];

// ---------------- fold weights + bias table ----------------
__global__ void fold_kernel(const float* __restrict__ Wq, const float* __restrict__ Wk,
                            const float* __restrict__ Wv, const float* __restrict__ Wo,
                            const float* __restrict__ rb) {
    int idx = blockIdx.x * blockDim.x + threadIdx.x;
    if (idx < 256 * 1024) {
        int r   = idx >> 10;      // 0..255
        int col = idx & 1023;
        int h = r >> 6, d = r & 63;
        float sq = 0.f, sk = 0.f, sv = 0.f;
        #pragma unroll
        for (int g = 0; g < 4; g++) {
            int src = ((g * 4 + h) * 64 + d) * 1024 + col;
            sq += Wq[src]; sk += Wk[src]; sv += Wv[src];
        }
        g_Wf[(size_t)r * 1024 + col]         = sq;
        g_Wf[(size_t)(256 + r) * 1024 + col] = sk * 0.25f;
        g_Wf[(size_t)(512 + r) * 1024 + col] = sv * 0.25f;

        int j = idx >> 8;         // 0..1023
        int c = idx & 255;
        float so = 0.f;
        #pragma unroll
        for (int g = 0; g < 4; g++) so += Wo[j * 1024 + g * 256 + c];
        g_WoS[idx] = so;
    }
    if (idx < 4095 * 4) {
        int i = idx >> 2, h = idx & 3;
        int rel = i - 2047;
        int bucket = (rel > 0) ? 16 : 0;
        int rp = rel < 0 ? -rel : rel;
        int lb;
        if (rp < 8) lb = rp;
        else {
            int cnt = (rp >= 12) + (rp >= 16) + (rp >= 23) + (rp >= 32) +
                      (rp >= 46) + (rp >= 64) + (rp >= 91);
            lb = 8 + cnt;
        }
        bucket += lb;
        float s = 0.f;
        #pragma unroll
        for (int g = 0; g < 4; g++) s += rb[bucket * 16 + g * 4 + h];
        g_bias[idx] = s * 0.25f;
    }
}

// ---------------- tf32 helpers ----------------
__device__ __forceinline__ unsigned f2tf(float x) {
    unsigned r; asm("cvt.rna.tf32.f32 %0, %1;" : "=r"(r) : "f"(x)); return r;
}

#define MMA_TF32(d, a, b0, b1)                                              \
    asm volatile("mma.sync.aligned.m16n8k8.row.col.f32.tf32.tf32.f32 "      \
        "{%0,%1,%2,%3}, {%4,%5,%6,%7}, {%8,%9}, {%0,%1,%2,%3};"             \
        : "+f"(d[0]), "+f"(d[1]), "+f"(d[2]), "+f"(d[3])                    \
        : "r"(a[0]), "r"(a[1]), "r"(a[2]), "r"(a[3]), "r"(b0), "r"(b1))

// ---------------- 3xTF32 GEMM: C[M,N] = A[M,K] * B[N,K]^T ----------------
// BM=128, BN=64, BK=32; 256 threads = 8 warps in 4(m) x 2(n); warp tile 32x32.
// mode 0: plain C [M,N].  mode 1: QKV split — col>>8 selects Qp/Kp/Vp, stride 256.
__global__ __launch_bounds__(256, 2)
void gemm_tf32(const float* __restrict__ A, const float* __restrict__ B,
               float* __restrict__ C,
               float* __restrict__ Qp, float* __restrict__ Kp, float* __restrict__ Vp,
               int M, int N, int K, int mode) {
    extern __shared__ float sm[];
    float* Ah = sm;                      // [BM][LDT]
    float* Al = Ah + BM * LDT;
    float* Bh = Al + BM * LDT;           // [BN][LDT]
    float* Bl = Bh + BN * LDT;

    int tid  = threadIdx.x;
    int lane = tid & 31, warp = tid >> 5;
    int wm = warp >> 1, wn = warp & 1;
    int gid = lane >> 2, tig = lane & 3;
    int m0 = blockIdx.y * BM, n0 = blockIdx.x * BN;

    float acc[2][4][4];
    #pragma unroll
    for (int mi = 0; mi < 2; mi++)
        #pragma unroll
        for (int ni = 0; ni < 4; ni++)
            #pragma unroll
            for (int r = 0; r < 4; r++) acc[mi][ni][r] = 0.f;

    for (int kt = 0; kt < K; kt += BK) {
        // A tile: 128x32 = 1024 float4, 4 per thread; split hi/lo into smem
        #pragma unroll
        for (int p = 0; p < 4; p++) {
            int f = tid + p * 256;
            int row = f >> 3, seg = (f & 7) * 4;
            float4 v = *(const float4*)(A + (size_t)(m0 + row) * K + kt + seg);
            float h0 = __uint_as_float(f2tf(v.x));
            float h1 = __uint_as_float(f2tf(v.y));
            float h2 = __uint_as_float(f2tf(v.z));
            float h3 = __uint_as_float(f2tf(v.w));
            float* ah = Ah + row * LDT + seg;
            float* al = Al + row * LDT + seg;
            ah[0] = h0; ah[1] = h1; ah[2] = h2; ah[3] = h3;
            al[0] = __uint_as_float(f2tf(v.x - h0));
            al[1] = __uint_as_float(f2tf(v.y - h1));
            al[2] = __uint_as_float(f2tf(v.z - h2));
            al[3] = __uint_as_float(f2tf(v.w - h3));
        }
        // B tile: 64x32 = 512 float4, 2 per thread
        #pragma unroll
        for (int p = 0; p < 2; p++) {
            int f = tid + p * 256;
            int row = f >> 3, seg = (f & 7) * 4;
            float4 v = *(const float4*)(B + (size_t)(n0 + row) * K + kt + seg);
            float h0 = __uint_as_float(f2tf(v.x));
            float h1 = __uint_as_float(f2tf(v.y));
            float h2 = __uint_as_float(f2tf(v.z));
            float h3 = __uint_as_float(f2tf(v.w));
            float* bh = Bh + row * LDT + seg;
            float* bl = Bl + row * LDT + seg;
            bh[0] = h0; bh[1] = h1; bh[2] = h2; bh[3] = h3;
            bl[0] = __uint_as_float(f2tf(v.x - h0));
            bl[1] = __uint_as_float(f2tf(v.y - h1));
            bl[2] = __uint_as_float(f2tf(v.z - h2));
            bl[3] = __uint_as_float(f2tf(v.w - h3));
        }
        __syncthreads();

        #pragma unroll
        for (int ks = 0; ks < BK / 8; ks++) {
            int k = ks * 8;
            unsigned ah[2][4], al[2][4];
            #pragma unroll
            for (int mi = 0; mi < 2; mi++) {
                int rb = wm * 32 + mi * 16;
                const float* a0 = Ah + (rb + gid) * LDT + k + tig;
                const float* a1 = Ah + (rb + gid + 8) * LDT + k + tig;
                ah[mi][0] = __float_as_uint(a0[0]);
                ah[mi][1] = __float_as_uint(a1[0]);
                ah[mi][2] = __float_as_uint(a0[4]);
                ah[mi][3] = __float_as_uint(a1[4]);
                const float* l0 = Al + (rb + gid) * LDT + k + tig;
                const float* l1 = Al + (rb + gid + 8) * LDT + k + tig;
                al[mi][0] = __float_as_uint(l0[0]);
                al[mi][1] = __float_as_uint(l1[0]);
                al[mi][2] = __float_as_uint(l0[4]);
                al[mi][3] = __float_as_uint(l1[4]);
            }
            #pragma unroll
            for (int ni = 0; ni < 4; ni++) {
                int cb = wn * 32 + ni * 8 + gid;
                unsigned bh0 = __float_as_uint(Bh[cb * LDT + k + tig]);
                unsigned bh1 = __float_as_uint(Bh[cb * LDT + k + tig + 4]);
                unsigned bl0 = __float_as_uint(Bl[cb * LDT + k + tig]);
                unsigned bl1 = __float_as_uint(Bl[cb * LDT + k + tig + 4]);
                #pragma unroll
                for (int mi = 0; mi < 2; mi++) {
                    MMA_TF32(acc[mi][ni], ah[mi], bh0, bh1);
                    MMA_TF32(acc[mi][ni], ah[mi], bl0, bl1);
                    MMA_TF32(acc[mi][ni], al[mi], bh0, bh1);
                }
            }
        }
        __syncthreads();
    }

    // epilogue
    #pragma unroll
    for (int mi = 0; mi < 2; mi++) {
        #pragma unroll
        for (int ni = 0; ni < 4; ni++) {
            int row0 = m0 + wm * 32 + mi * 16 + gid;
            int ncol = n0 + wn * 32 + ni * 8 + tig * 2;
            float2 v01 = make_float2(acc[mi][ni][0], acc[mi][ni][1]);
            float2 v23 = make_float2(acc[mi][ni][2], acc[mi][ni][3]);
            if (mode == 0) {
                *(float2*)(C + (size_t)row0 * N + ncol)       = v01;
                *(float2*)(C + (size_t)(row0 + 8) * N + ncol) = v23;
            } else {
                int buf = ncol >> 8, rem = ncol & 255;
                float* dst = (buf == 0) ? Qp : (buf == 1) ? Kp : Vp;
                *(float2*)(dst + (size_t)row0 * DKV + rem)       = v01;
                *(float2*)(dst + (size_t)(row0 + 8) * DKV + rem) = v23;
            }
        }
    }
}

// ---------------- flash attention (unchanged, fp32) ----------------
__global__ void attn_kernel() {
    extern __shared__ float sm[];
    float* Qs = sm;
    float* Ks = sm + 64 * AP;
    float* Vs = sm + 2 * 64 * AP;
    float* Ps = sm + 3 * 64 * AP;

    int tid = threadIdx.x;
    int tx = tid & 15, ty = tid >> 4;
    int q0 = blockIdx.x * 64;
    int bh = blockIdx.y;
    int b = bh >> 2, h = bh & 3;

    const float* Qg = g_Q + ((size_t)(b * N_TOK + q0)) * DKV + h * 64;
    #pragma unroll
    for (int p = 0; p < 4; p++) {
        int e = tid + p * 256;
        int row = e >> 4, seg = (e & 15) * 4;
        float4 v = *(const float4*)(Qg + (size_t)row * DKV + seg);
        Qs[row * AP + seg + 0] = v.x; Qs[row * AP + seg + 1] = v.y;
        Qs[row * AP + seg + 2] = v.z; Qs[row * AP + seg + 3] = v.w;
    }

    float m_i[4], l_i[4], acc[4][4];
    #pragma unroll
    for (int i = 0; i < 4; i++) {
        m_i[i] = -CUDART_INF_F; l_i[i] = 0.f;
        #pragma unroll
        for (int j = 0; j < 4; j++) acc[i][j] = 0.f;
    }
    __syncthreads();

    for (int kv0 = 0; kv0 < N_TOK; kv0 += 64) {
        const float* Kg = g_K + ((size_t)(b * N_TOK + kv0)) * DKV + h * 64;
        const float* Vg = g_V + ((size_t)(b * N_TOK + kv0)) * DKV + h * 64;
        #pragma unroll
        for (int p = 0; p < 4; p++) {
            int e = tid + p * 256;
            int row = e >> 4, seg = (e & 15) * 4;
            float4 kv = *(const float4*)(Kg + (size_t)row * DKV + seg);
            Ks[row * AP + seg + 0] = kv.x; Ks[row * AP + seg + 1] = kv.y;
            Ks[row * AP + seg + 2] = kv.z; Ks[row * AP + seg + 3] = kv.w;
            float4 vv = *(const float4*)(Vg + (size_t)row * DKV + seg);
            Vs[row * AP + seg + 0] = vv.x; Vs[row * AP + seg + 1] = vv.y;
            Vs[row * AP + seg + 2] = vv.z; Vs[row * AP + seg + 3] = vv.w;
        }
        __syncthreads();

        float s[4][4] = {};
        #pragma unroll
        for (int d = 0; d < 64; d++) {
            float qv[4], kvv[4];
            #pragma unroll
            for (int i = 0; i < 4; i++) qv[i]  = Qs[(ty * 4 + i) * AP + d];
            #pragma unroll
            for (int j = 0; j < 4; j++) kvv[j] = Ks[(tx * 4 + j) * AP + d];
            #pragma unroll
            for (int i = 0; i < 4; i++)
                #pragma unroll
                for (int j = 0; j < 4; j++) s[i][j] += qv[i] * kvv[j];
        }
        #pragma unroll
        for (int i = 0; i < 4; i++)
            #pragma unroll
            for (int j = 0; j < 4; j++)
                s[i][j] += g_bias[((kv0 + tx * 4 + j) - (q0 + ty * 4 + i) + 2047) * 4 + h];

        float alpha[4];
        #pragma unroll
        for (int i = 0; i < 4; i++) {
            float mx = fmaxf(fmaxf(s[i][0], s[i][1]), fmaxf(s[i][2], s[i][3]));
            #pragma unroll
            for (int off = 8; off; off >>= 1)
                mx = fmaxf(mx, __shfl_xor_sync(0xffffffffu, mx, off, 16));
            float mnew = fmaxf(m_i[i], mx);
            alpha[i] = expf(m_i[i] - mnew);
            float ps = 0.f;
            #pragma unroll
            for (int j = 0; j < 4; j++) { s[i][j] = expf(s[i][j] - mnew); ps += s[i][j]; }
            #pragma unroll
            for (int off = 8; off; off >>= 1)
                ps += __shfl_xor_sync(0xffffffffu, ps, off, 16);
            l_i[i] = l_i[i] * alpha[i] + ps;
            m_i[i] = mnew;
        }
        #pragma unroll
        for (int i = 0; i < 4; i++)
            #pragma unroll
            for (int j = 0; j < 4; j++)
                Ps[(ty * 4 + i) * AP + tx * 4 + j] = s[i][j];
        __syncthreads();

        #pragma unroll
        for (int i = 0; i < 4; i++)
            #pragma unroll
            for (int j = 0; j < 4; j++) acc[i][j] *= alpha[i];
        #pragma unroll 8
        for (int ss = 0; ss < 64; ss++) {
            float pv[4], vv[4];
            #pragma unroll
            for (int i = 0; i < 4; i++) pv[i] = Ps[(ty * 4 + i) * AP + ss];
            #pragma unroll
            for (int j = 0; j < 4; j++) vv[j] = Vs[ss * AP + tx * 4 + j];
            #pragma unroll
            for (int i = 0; i < 4; i++)
                #pragma unroll
                for (int j = 0; j < 4; j++) acc[i][j] += pv[i] * vv[j];
        }
        __syncthreads();
    }

    float* Og = g_O + ((size_t)(b * N_TOK + q0)) * DKV + h * 64;
    #pragma unroll
    for (int i = 0; i < 4; i++) {
        float inv = 1.f / l_i[i];
        #pragma unroll
        for (int j = 0; j < 4; j++)
            Og[(size_t)(ty * 4 + i) * DKV + tx * 4 + j] = acc[i][j] * inv;
    }
}

// ---------------- launch ----------------
extern "C" void kernel_launch(void* const* d_in, const int* in_sizes, int n_in,
                              void* d_out, int out_size) {
    const float* hs = (const float*)d_in[0];
    const float* Wq = (const float*)d_in[1];
    const float* Wk = (const float*)d_in[2];
    const float* Wv = (const float*)d_in[3];
    const float* Wo = (const float*)d_in[4];
    const float* rb = (const float*)d_in[5];
    float* out = (float*)d_out;

    void *pWf, *pWoS, *pQ, *pK, *pV, *pO;
    cudaGetSymbolAddress(&pWf, g_Wf);
    cudaGetSymbolAddress(&pWoS, g_WoS);
    cudaGetSymbolAddress(&pQ, g_Q);
    cudaGetSymbolAddress(&pK, g_K);
    cudaGetSymbolAddress(&pV, g_V);
    cudaGetSymbolAddress(&pO, g_O);

    fold_kernel<<<1024, 256>>>(Wq, Wk, Wv, Wo, rb);

    int gsmem = (2 * BM + 2 * BN) * LDT * sizeof(float);   // 55296
    cudaFuncSetAttribute(gemm_tf32, cudaFuncAttributeMaxDynamicSharedMemorySize, gsmem);

    // fused QKV projection: [8192, 768] = hs @ Wf^T
    gemm_tf32<<<dim3(768 / BN, M_TOTAL / BM), 256, gsmem>>>(
        hs, (const float*)pWf, nullptr,
        (float*)pQ, (float*)pK, (float*)pV, M_TOTAL, 768, DM, 1);

    int asmem = 4 * 64 * AP * sizeof(float);
    cudaFuncSetAttribute(attn_kernel, cudaFuncAttributeMaxDynamicSharedMemorySize, asmem);
    attn_kernel<<<dim3(N_TOK / 64, BATCH * 4), 256, asmem>>>();

    // output: [8192, 1024] = O @ WoS^T
    gemm_tf32<<<dim3(DM / BN, M_TOTAL / BM), 256, gsmem>>>(
        (const float*)pO, (const float*)pWoS, out,
        nullptr, nullptr, nullptr, M_TOTAL, DM, DKV, 0);
}

// round 5
// speedup vs baseline: 2.0402x; 1.6028x over previous
#include <cuda_runtime.h>
#include <cuda_bf16.h>
#include <math_constants.h>
#include <cstddef>

#define N_TOK 2048
#define BATCH 4
#define DM    1024
#define DKV   256
#define M_TOTAL (BATCH * N_TOK)   // 8192
#define LOG2E 1.4426950408889634f

#define BM 128
#define BN 64
#define BK 32
#define LDT 36                    // gemm smem stride

// attention tile params
#define QT 128                    // q rows per block
#define KT 64                     // keys per tile
#define LDA 68                    // f32 smem stride (64+4)
#define LDV 72                    // bf16 smem stride in halves (64+8)

// ---------------- scratch ----------------
__device__ float g_Wf[768 * 1024];
__device__ float g_WoS[1024 * 256];
__device__ float g_bias[4095 * 4];
__device__ float g_Q[M_TOTAL * DKV];
__device__ float g_K[M_TOTAL * DKV];
__device__ float g_V[M_TOTAL * DKV];
__device__ float g_O[M_TOTAL * DKV];

// ---------------- fold weights + bias table ----------------
__global__ void fold_kernel(const float* __restrict__ Wq, const float* __restrict__ Wk,
                            const float* __restrict__ Wv, const float* __restrict__ Wo,
                            const float* __restrict__ rb) {
    int idx = blockIdx.x * blockDim.x + threadIdx.x;
    if (idx < 256 * 1024) {
        int r   = idx >> 10;
        int col = idx & 1023;
        int h = r >> 6, d = r & 63;
        float sq = 0.f, sk = 0.f, sv = 0.f;
        #pragma unroll
        for (int g = 0; g < 4; g++) {
            int src = ((g * 4 + h) * 64 + d) * 1024 + col;
            sq += Wq[src]; sk += Wk[src]; sv += Wv[src];
        }
        g_Wf[(size_t)r * 1024 + col]         = sq;
        g_Wf[(size_t)(256 + r) * 1024 + col] = sk * 0.25f;
        g_Wf[(size_t)(512 + r) * 1024 + col] = sv * 0.25f;

        int j = idx >> 8;
        int c = idx & 255;
        float so = 0.f;
        #pragma unroll
        for (int g = 0; g < 4; g++) so += Wo[j * 1024 + g * 256 + c];
        g_WoS[idx] = so;
    }
    if (idx < 4095 * 4) {
        int i = idx >> 2, h = idx & 3;
        int rel = i - 2047;
        int bucket = (rel > 0) ? 16 : 0;
        int rp = rel < 0 ? -rel : rel;
        int lb;
        if (rp < 8) lb = rp;
        else {
            int cnt = (rp >= 12) + (rp >= 16) + (rp >= 23) + (rp >= 32) +
                      (rp >= 46) + (rp >= 64) + (rp >= 91);
            lb = 8 + cnt;
        }
        bucket += lb;
        float s = 0.f;
        #pragma unroll
        for (int g = 0; g < 4; g++) s += rb[bucket * 16 + g * 4 + h];
        g_bias[idx] = s * 0.25f * LOG2E;      // pre-scale to log2 domain
    }
}

// ---------------- PTX helpers ----------------
__device__ __forceinline__ unsigned f2tf(float x) {
    unsigned r; asm("cvt.rna.tf32.f32 %0, %1;" : "=r"(r) : "f"(x)); return r;
}

#define MMA_TF32(d, a, b0, b1)                                              \
    asm volatile("mma.sync.aligned.m16n8k8.row.col.f32.tf32.tf32.f32 "      \
        "{%0,%1,%2,%3}, {%4,%5,%6,%7}, {%8,%9}, {%0,%1,%2,%3};"             \
        : "+f"(d[0]), "+f"(d[1]), "+f"(d[2]), "+f"(d[3])                    \
        : "r"(a[0]), "r"(a[1]), "r"(a[2]), "r"(a[3]), "r"(b0), "r"(b1))

#define MMA_BF16(d, a, b0, b1)                                              \
    asm volatile("mma.sync.aligned.m16n8k16.row.col.f32.bf16.bf16.f32 "     \
        "{%0,%1,%2,%3}, {%4,%5,%6,%7}, {%8,%9}, {%0,%1,%2,%3};"             \
        : "+f"(d[0]), "+f"(d[1]), "+f"(d[2]), "+f"(d[3])                    \
        : "r"(a[0]), "r"(a[1]), "r"(a[2]), "r"(a[3]), "r"(b0), "r"(b1))

__device__ __forceinline__ void ldsm2t(unsigned& r0, unsigned& r1, const void* p) {
    unsigned a = (unsigned)__cvta_generic_to_shared(p);
    asm volatile("ldmatrix.sync.aligned.m8n8.x2.trans.shared.b16 {%0,%1}, [%2];"
                 : "=r"(r0), "=r"(r1) : "r"(a));
}

// pack {lo_elem, hi_elem} -> bf16x2 (low half = first element)
__device__ __forceinline__ unsigned pk2(float e0, float e1) {
    unsigned r; asm("cvt.rn.bf16x2.f32 %0, %1, %2;" : "=r"(r) : "f"(e1), "f"(e0)); return r;
}

// FMA-pipe exp2 (no MUFU). t <= 0 expected; clamps below -126.
__device__ __forceinline__ float exp2p(float t) {
    t = fmaxf(t, -126.f);
    float r = rintf(t);
    float f = t - r;
    int   i = (int)r;
    float p = 1.5403530e-4f;
    p = fmaf(p, f, 1.3333558e-3f);
    p = fmaf(p, f, 9.6181291e-3f);
    p = fmaf(p, f, 5.5504109e-2f);
    p = fmaf(p, f, 2.4022651e-1f);
    p = fmaf(p, f, 6.9314718e-1f);
    p = fmaf(p, f, 1.0f);
    return p * __int_as_float((i + 127) << 23);
}

// ---------------- 3xTF32 GEMM (unchanged, validated) ----------------
__global__ __launch_bounds__(256, 2)
void gemm_tf32(const float* __restrict__ A, const float* __restrict__ B,
               float* __restrict__ C,
               float* __restrict__ Qp, float* __restrict__ Kp, float* __restrict__ Vp,
               int M, int N, int K, int mode) {
    extern __shared__ float sm[];
    float* Ah = sm;
    float* Al = Ah + BM * LDT;
    float* Bh = Al + BM * LDT;
    float* Bl = Bh + BN * LDT;

    int tid  = threadIdx.x;
    int lane = tid & 31, warp = tid >> 5;
    int wm = warp >> 1, wn = warp & 1;
    int gid = lane >> 2, tig = lane & 3;
    int m0 = blockIdx.y * BM, n0 = blockIdx.x * BN;

    float acc[2][4][4];
    #pragma unroll
    for (int mi = 0; mi < 2; mi++)
        #pragma unroll
        for (int ni = 0; ni < 4; ni++)
            #pragma unroll
            for (int r = 0; r < 4; r++) acc[mi][ni][r] = 0.f;

    for (int kt = 0; kt < K; kt += BK) {
        #pragma unroll
        for (int p = 0; p < 4; p++) {
            int f = tid + p * 256;
            int row = f >> 3, seg = (f & 7) * 4;
            float4 v = *(const float4*)(A + (size_t)(m0 + row) * K + kt + seg);
            float h0 = __uint_as_float(f2tf(v.x));
            float h1 = __uint_as_float(f2tf(v.y));
            float h2 = __uint_as_float(f2tf(v.z));
            float h3 = __uint_as_float(f2tf(v.w));
            float* ah = Ah + row * LDT + seg;
            float* al = Al + row * LDT + seg;
            ah[0] = h0; ah[1] = h1; ah[2] = h2; ah[3] = h3;
            al[0] = __uint_as_float(f2tf(v.x - h0));
            al[1] = __uint_as_float(f2tf(v.y - h1));
            al[2] = __uint_as_float(f2tf(v.z - h2));
            al[3] = __uint_as_float(f2tf(v.w - h3));
        }
        #pragma unroll
        for (int p = 0; p < 2; p++) {
            int f = tid + p * 256;
            int row = f >> 3, seg = (f & 7) * 4;
            float4 v = *(const float4*)(B + (size_t)(n0 + row) * K + kt + seg);
            float h0 = __uint_as_float(f2tf(v.x));
            float h1 = __uint_as_float(f2tf(v.y));
            float h2 = __uint_as_float(f2tf(v.z));
            float h3 = __uint_as_float(f2tf(v.w));
            float* bh = Bh + row * LDT + seg;
            float* bl = Bl + row * LDT + seg;
            bh[0] = h0; bh[1] = h1; bh[2] = h2; bh[3] = h3;
            bl[0] = __uint_as_float(f2tf(v.x - h0));
            bl[1] = __uint_as_float(f2tf(v.y - h1));
            bl[2] = __uint_as_float(f2tf(v.z - h2));
            bl[3] = __uint_as_float(f2tf(v.w - h3));
        }
        __syncthreads();

        #pragma unroll
        for (int ks = 0; ks < BK / 8; ks++) {
            int k = ks * 8;
            unsigned ah[2][4], al[2][4];
            #pragma unroll
            for (int mi = 0; mi < 2; mi++) {
                int rb = wm * 32 + mi * 16;
                const float* a0 = Ah + (rb + gid) * LDT + k + tig;
                const float* a1 = Ah + (rb + gid + 8) * LDT + k + tig;
                ah[mi][0] = __float_as_uint(a0[0]);
                ah[mi][1] = __float_as_uint(a1[0]);
                ah[mi][2] = __float_as_uint(a0[4]);
                ah[mi][3] = __float_as_uint(a1[4]);
                const float* l0 = Al + (rb + gid) * LDT + k + tig;
                const float* l1 = Al + (rb + gid + 8) * LDT + k + tig;
                al[mi][0] = __float_as_uint(l0[0]);
                al[mi][1] = __float_as_uint(l1[0]);
                al[mi][2] = __float_as_uint(l0[4]);
                al[mi][3] = __float_as_uint(l1[4]);
            }
            #pragma unroll
            for (int ni = 0; ni < 4; ni++) {
                int cb = wn * 32 + ni * 8 + gid;
                unsigned bh0 = __float_as_uint(Bh[cb * LDT + k + tig]);
                unsigned bh1 = __float_as_uint(Bh[cb * LDT + k + tig + 4]);
                unsigned bl0 = __float_as_uint(Bl[cb * LDT + k + tig]);
                unsigned bl1 = __float_as_uint(Bl[cb * LDT + k + tig + 4]);
                #pragma unroll
                for (int mi = 0; mi < 2; mi++) {
                    MMA_TF32(acc[mi][ni], ah[mi], bh0, bh1);
                    MMA_TF32(acc[mi][ni], ah[mi], bl0, bl1);
                    MMA_TF32(acc[mi][ni], al[mi], bh0, bh1);
                }
            }
        }
        __syncthreads();
    }

    #pragma unroll
    for (int mi = 0; mi < 2; mi++) {
        #pragma unroll
        for (int ni = 0; ni < 4; ni++) {
            int row0 = m0 + wm * 32 + mi * 16 + gid;
            int ncol = n0 + wn * 32 + ni * 8 + tig * 2;
            float2 v01 = make_float2(acc[mi][ni][0], acc[mi][ni][1]);
            float2 v23 = make_float2(acc[mi][ni][2], acc[mi][ni][3]);
            if (mode == 0) {
                *(float2*)(C + (size_t)row0 * N + ncol)       = v01;
                *(float2*)(C + (size_t)(row0 + 8) * N + ncol) = v23;
            } else {
                int buf = ncol >> 8, rem = ncol & 255;
                float* dst = (buf == 0) ? Qp : (buf == 1) ? Kp : Vp;
                *(float2*)(dst + (size_t)row0 * DKV + rem)       = v01;
                *(float2*)(dst + (size_t)(row0 + 8) * DKV + rem) = v23;
            }
        }
    }
}

// ---------------- tensor-core flash attention ----------------
// 128 q-rows/block, 64-key tiles, 8 warps x (16 rows, 64 cols).
// QK^T: 3xTF32 m16n8k8. PV: bf16 hi/lo m16n8k16 (P stays in registers).
// Softmax in log2 domain (Q and bias pre-scaled by log2e); exp2 on FMA pipe.
__global__ __launch_bounds__(256, 1)
void attn_tc() {
    extern __shared__ float sm[];
    float* Qh = sm;                              // [128][68]
    float* Ql = Qh + QT * LDA;
    float* Kh = Ql + QT * LDA;                   // [64][68]
    float* Kl = Kh + KT * LDA;
    __nv_bfloat16* Vh = (__nv_bfloat16*)(Kl + KT * LDA);   // [64][72] halves
    __nv_bfloat16* Vl = Vh + KT * LDV;
    float* biass = (float*)(Vl + KT * LDV);      // [2176]

    int tid = threadIdx.x;
    int lane = tid & 31, w = tid >> 5;
    int gid = lane >> 2, tig = lane & 3;
    int q0 = blockIdx.x * QT;
    int bh = blockIdx.y;
    int b = bh >> 2, h = bh & 3;

    // bias window for whole block: biass[key + 127 - row_in_tile]
    for (int i = tid; i < 2176; i += 256) {
        int t = i - 127 - q0 + 2047;
        t = max(0, min(4094, t));
        biass[i] = g_bias[t * 4 + h];
    }

    // load Q tile (scaled by log2e), split hi/lo
    const float* Qg = g_Q + ((size_t)(b * N_TOK + q0)) * DKV + h * 64;
    #pragma unroll
    for (int p = 0; p < 8; p++) {
        int f = tid + p * 256;
        int row = f >> 4, seg = (f & 15) * 4;
        float4 v = *(const float4*)(Qg + (size_t)row * DKV + seg);
        v.x *= LOG2E; v.y *= LOG2E; v.z *= LOG2E; v.w *= LOG2E;
        float h0 = __uint_as_float(f2tf(v.x));
        float h1 = __uint_as_float(f2tf(v.y));
        float h2 = __uint_as_float(f2tf(v.z));
        float h3 = __uint_as_float(f2tf(v.w));
        float* qh = Qh + row * LDA + seg;
        float* ql = Ql + row * LDA + seg;
        qh[0] = h0; qh[1] = h1; qh[2] = h2; qh[3] = h3;
        ql[0] = __uint_as_float(f2tf(v.x - h0));
        ql[1] = __uint_as_float(f2tf(v.y - h1));
        ql[2] = __uint_as_float(f2tf(v.z - h2));
        ql[3] = __uint_as_float(f2tf(v.w - h3));
    }

    float m0r = -1e30f, m1r = -1e30f, l0r = 0.f, l1r = 0.f;
    float o[8][4];
    #pragma unroll
    for (int ni = 0; ni < 8; ni++)
        #pragma unroll
        for (int r = 0; r < 4; r++) o[ni][r] = 0.f;

    for (int kv0 = 0; kv0 < N_TOK; kv0 += KT) {
        __syncthreads();
        // load K (split tf32 hi/lo) and V (split bf16 hi/lo)
        const float* Kg = g_K + ((size_t)(b * N_TOK + kv0)) * DKV + h * 64;
        const float* Vg = g_V + ((size_t)(b * N_TOK + kv0)) * DKV + h * 64;
        #pragma unroll
        for (int p = 0; p < 4; p++) {
            int f = tid + p * 256;
            int row = f >> 4, seg = (f & 15) * 4;
            float4 kv = *(const float4*)(Kg + (size_t)row * DKV + seg);
            float h0 = __uint_as_float(f2tf(kv.x));
            float h1 = __uint_as_float(f2tf(kv.y));
            float h2 = __uint_as_float(f2tf(kv.z));
            float h3 = __uint_as_float(f2tf(kv.w));
            float* kh = Kh + row * LDA + seg;
            float* kl = Kl + row * LDA + seg;
            kh[0] = h0; kh[1] = h1; kh[2] = h2; kh[3] = h3;
            kl[0] = __uint_as_float(f2tf(kv.x - h0));
            kl[1] = __uint_as_float(f2tf(kv.y - h1));
            kl[2] = __uint_as_float(f2tf(kv.z - h2));
            kl[3] = __uint_as_float(f2tf(kv.w - h3));

            float4 vv = *(const float4*)(Vg + (size_t)row * DKV + seg);
            float ve[4] = {vv.x, vv.y, vv.z, vv.w};
            #pragma unroll
            for (int j = 0; j < 4; j++) {
                __nv_bfloat16 vb = __float2bfloat16(ve[j]);
                Vh[row * LDV + seg + j] = vb;
                Vl[row * LDV + seg + j] = __float2bfloat16(ve[j] - __bfloat162float(vb));
            }
        }
        __syncthreads();

        // ---- S = Q K^T (3xTF32) ----
        float s[8][4];
        #pragma unroll
        for (int ni = 0; ni < 8; ni++)
            #pragma unroll
            for (int r = 0; r < 4; r++) s[ni][r] = 0.f;

        int r0 = w * 16 + gid;
        #pragma unroll
        for (int ks = 0; ks < 8; ks++) {
            int k = ks * 8;
            unsigned ah[4], al[4];
            ah[0] = __float_as_uint(Qh[r0 * LDA + k + tig]);
            ah[1] = __float_as_uint(Qh[(r0 + 8) * LDA + k + tig]);
            ah[2] = __float_as_uint(Qh[r0 * LDA + k + tig + 4]);
            ah[3] = __float_as_uint(Qh[(r0 + 8) * LDA + k + tig + 4]);
            al[0] = __float_as_uint(Ql[r0 * LDA + k + tig]);
            al[1] = __float_as_uint(Ql[(r0 + 8) * LDA + k + tig]);
            al[2] = __float_as_uint(Ql[r0 * LDA + k + tig + 4]);
            al[3] = __float_as_uint(Ql[(r0 + 8) * LDA + k + tig + 4]);
            #pragma unroll
            for (int ni = 0; ni < 8; ni++) {
                int n = ni * 8 + gid;
                unsigned bh0 = __float_as_uint(Kh[n * LDA + k + tig]);
                unsigned bh1 = __float_as_uint(Kh[n * LDA + k + tig + 4]);
                unsigned bl0 = __float_as_uint(Kl[n * LDA + k + tig]);
                unsigned bl1 = __float_as_uint(Kl[n * LDA + k + tig + 4]);
                MMA_TF32(s[ni], ah, bh0, bh1);
                MMA_TF32(s[ni], ah, bl0, bl1);
                MMA_TF32(s[ni], al, bh0, bh1);
            }
        }

        // ---- bias add ----
        int boff0 = kv0 + 127 + 2 * tig - w * 16 - gid;
        #pragma unroll
        for (int ni = 0; ni < 8; ni++) {
            s[ni][0] += biass[boff0 + ni * 8];
            s[ni][1] += biass[boff0 + ni * 8 + 1];
            s[ni][2] += biass[boff0 + ni * 8 - 8];
            s[ni][3] += biass[boff0 + ni * 8 - 7];
        }

        // ---- online softmax (log2 domain) ----
        float mx0 = -1e30f, mx1 = -1e30f;
        #pragma unroll
        for (int ni = 0; ni < 8; ni++) {
            mx0 = fmaxf(mx0, fmaxf(s[ni][0], s[ni][1]));
            mx1 = fmaxf(mx1, fmaxf(s[ni][2], s[ni][3]));
        }
        mx0 = fmaxf(mx0, __shfl_xor_sync(0xffffffffu, mx0, 1));
        mx0 = fmaxf(mx0, __shfl_xor_sync(0xffffffffu, mx0, 2));
        mx1 = fmaxf(mx1, __shfl_xor_sync(0xffffffffu, mx1, 1));
        mx1 = fmaxf(mx1, __shfl_xor_sync(0xffffffffu, mx1, 2));
        float mn0 = fmaxf(m0r, mx0), mn1 = fmaxf(m1r, mx1);
        float a0 = exp2p(m0r - mn0), a1 = exp2p(m1r - mn1);
        m0r = mn0; m1r = mn1;

        float ps0 = 0.f, ps1 = 0.f;
        #pragma unroll
        for (int ni = 0; ni < 8; ni++) {
            s[ni][0] = exp2p(s[ni][0] - mn0); ps0 += s[ni][0];
            s[ni][1] = exp2p(s[ni][1] - mn0); ps0 += s[ni][1];
            s[ni][2] = exp2p(s[ni][2] - mn1); ps1 += s[ni][2];
            s[ni][3] = exp2p(s[ni][3] - mn1); ps1 += s[ni][3];
        }
        ps0 += __shfl_xor_sync(0xffffffffu, ps0, 1);
        ps0 += __shfl_xor_sync(0xffffffffu, ps0, 2);
        ps1 += __shfl_xor_sync(0xffffffffu, ps1, 1);
        ps1 += __shfl_xor_sync(0xffffffffu, ps1, 2);
        l0r = l0r * a0 + ps0;
        l1r = l1r * a1 + ps1;

        #pragma unroll
        for (int ni = 0; ni < 8; ni++) {
            o[ni][0] *= a0; o[ni][1] *= a0;
            o[ni][2] *= a1; o[ni][3] *= a1;
        }

        // ---- O += P V (bf16 hi/lo, P from registers) ----
        const __nv_bfloat16* vrow_h = Vh + (size_t)(lane & 15) * LDV;
        const __nv_bfloat16* vrow_l = Vl + (size_t)(lane & 15) * LDV;
        #pragma unroll
        for (int kk = 0; kk < 4; kk++) {
            unsigned pa[4], pl[4];
            #pragma unroll
            for (int q = 0; q < 2; q++) {           // q=0 -> s[2kk], q=1 -> s[2kk+1]
                float v0 = s[2 * kk + q][0], v1 = s[2 * kk + q][1];
                float v2 = s[2 * kk + q][2], v3 = s[2 * kk + q][3];
                unsigned hp0 = pk2(v0, v1);
                unsigned hp1 = pk2(v2, v3);
                pa[2 * q + 0] = hp0;
                pa[2 * q + 1] = hp1;
                float h0f = __uint_as_float(hp0 << 16);
                float h1f = __uint_as_float(hp0 & 0xffff0000u);
                float h2f = __uint_as_float(hp1 << 16);
                float h3f = __uint_as_float(hp1 & 0xffff0000u);
                pl[2 * q + 0] = pk2(v0 - h0f, v1 - h1f);
                pl[2 * q + 1] = pk2(v2 - h2f, v3 - h3f);
            }
            // A frag order for m16n8k16: a0=(gid,k lo), a1=(gid+8,k lo), a2=(gid,k hi), a3=(gid+8,k hi)
            unsigned ah[4] = {pa[0], pa[1], pa[2], pa[3]};
            unsigned alo[4] = {pl[0], pl[1], pl[2], pl[3]};
            const __nv_bfloat16* ph = vrow_h + (size_t)kk * 16 * LDV;
            const __nv_bfloat16* pll = vrow_l + (size_t)kk * 16 * LDV;
            #pragma unroll
            for (int ni = 0; ni < 8; ni++) {
                unsigned bh0, bh1, bl0, bl1;
                ldsm2t(bh0, bh1, ph + ni * 8);
                ldsm2t(bl0, bl1, pll + ni * 8);
                MMA_BF16(o[ni], ah, bh0, bh1);
                MMA_BF16(o[ni], alo, bh0, bh1);
                MMA_BF16(o[ni], ah, bl0, bl1);
            }
        }
    }

    // epilogue
    float inv0 = 1.f / l0r, inv1 = 1.f / l1r;
    float* Og = g_O + ((size_t)(b * N_TOK + q0 + w * 16 + gid)) * DKV + h * 64;
    #pragma unroll
    for (int ni = 0; ni < 8; ni++) {
        int c = ni * 8 + 2 * tig;
        *(float2*)(Og + c)             = make_float2(o[ni][0] * inv0, o[ni][1] * inv0);
        *(float2*)(Og + 8 * DKV + c)   = make_float2(o[ni][2] * inv1, o[ni][3] * inv1);
    }
}

// ---------------- launch ----------------
extern "C" void kernel_launch(void* const* d_in, const int* in_sizes, int n_in,
                              void* d_out, int out_size) {
    const float* hs = (const float*)d_in[0];
    const float* Wq = (const float*)d_in[1];
    const float* Wk = (const float*)d_in[2];
    const float* Wv = (const float*)d_in[3];
    const float* Wo = (const float*)d_in[4];
    const float* rb = (const float*)d_in[5];
    float* out = (float*)d_out;

    void *pWf, *pWoS, *pQ, *pK, *pV, *pO;
    cudaGetSymbolAddress(&pWf, g_Wf);
    cudaGetSymbolAddress(&pWoS, g_WoS);
    cudaGetSymbolAddress(&pQ, g_Q);
    cudaGetSymbolAddress(&pK, g_K);
    cudaGetSymbolAddress(&pV, g_V);
    cudaGetSymbolAddress(&pO, g_O);

    fold_kernel<<<1024, 256>>>(Wq, Wk, Wv, Wo, rb);

    int gsmem = (2 * BM + 2 * BN) * LDT * sizeof(float);
    cudaFuncSetAttribute(gemm_tf32, cudaFuncAttributeMaxDynamicSharedMemorySize, gsmem);
    gemm_tf32<<<dim3(768 / BN, M_TOTAL / BM), 256, gsmem>>>(
        hs, (const float*)pWf, nullptr,
        (float*)pQ, (float*)pK, (float*)pV, M_TOTAL, 768, DM, 1);

    // attention smem: Q(2) + K(2) f32 @LDA, V(2) bf16 @LDV, bias 2176 f32
    int asmem = (QT * LDA * 2 + KT * LDA * 2) * 4 + KT * LDV * 2 * 2 + 2176 * 4;
    cudaFuncSetAttribute(attn_tc, cudaFuncAttributeMaxDynamicSharedMemorySize, asmem);
    attn_tc<<<dim3(N_TOK / QT, BATCH * 4), 256, asmem>>>();

    gemm_tf32<<<dim3(DM / BN, M_TOTAL / BM), 256, gsmem>>>(
        (const float*)pO, (const float*)pWoS, out,
        nullptr, nullptr, nullptr, M_TOTAL, DM, DKV, 0);
}

// round 7
// speedup vs baseline: 2.3121x; 1.1333x over previous
#include <cuda_runtime.h>
#include <cuda_bf16.h>
#include <cstdint>
#include <cstddef>

#define N_TOK 2048
#define BATCH 4
#define DM    1024
#define DKV   256
#define M_TOTAL (BATCH * N_TOK)   // 8192
#define LOG2E 1.4426950408889634f

#define BM 128
#define BN 64
#define BK 32
#define LDT 36                    // gemm smem stride

// ---- attention tiles (all bf16 hi/lo, SW128 swizzled 128B rows) ----
#define QT 128
#define KT 64
#define SM_QH 0
#define SM_QL (SM_QH + 128 * 128)     // 16384
#define SM_KH (SM_QL + 128 * 128)     // 32768
#define SM_KL (SM_KH + 64 * 128)      // 40960
#define SM_VH (SM_KL + 64 * 128)      // 49152
#define SM_VL (SM_VH + 64 * 128)      // 57344
#define SM_BI (SM_VL + 64 * 128)      // 65536
#define SM_TOT (SM_BI + 2176 * 4)     // 74240 bytes -> 2 CTAs/SM

// ---------------- scratch ----------------
__device__ float g_Wf[768 * 1024];
__device__ float g_WoS[1024 * 256];
__device__ float g_bias[4095 * 4];
__device__ float g_Q[M_TOTAL * DKV];
__device__ float g_K[M_TOTAL * DKV];
__device__ float g_V[M_TOTAL * DKV];
__device__ float g_O[M_TOTAL * DKV];

// ---------------- fold weights + bias table ----------------
__global__ void fold_kernel(const float* __restrict__ Wq, const float* __restrict__ Wk,
                            const float* __restrict__ Wv, const float* __restrict__ Wo,
                            const float* __restrict__ rb) {
    int idx = blockIdx.x * blockDim.x + threadIdx.x;
    if (idx < 256 * 1024) {
        int r   = idx >> 10;
        int col = idx & 1023;
        int h = r >> 6, d = r & 63;
        float sq = 0.f, sk = 0.f, sv = 0.f;
        #pragma unroll
        for (int g = 0; g < 4; g++) {
            int src = ((g * 4 + h) * 64 + d) * 1024 + col;
            sq += Wq[src]; sk += Wk[src]; sv += Wv[src];
        }
        g_Wf[(size_t)r * 1024 + col]         = sq;
        g_Wf[(size_t)(256 + r) * 1024 + col] = sk * 0.25f;
        g_Wf[(size_t)(512 + r) * 1024 + col] = sv * 0.25f;

        int j = idx >> 8;
        int c = idx & 255;
        float so = 0.f;
        #pragma unroll
        for (int g = 0; g < 4; g++) so += Wo[j * 1024 + g * 256 + c];
        g_WoS[idx] = so;
    }
    if (idx < 4095 * 4) {
        int i = idx >> 2, h = idx & 3;
        int rel = i - 2047;
        int bucket = (rel > 0) ? 16 : 0;
        int rp = rel < 0 ? -rel : rel;
        int lb;
        if (rp < 8) lb = rp;
        else {
            int cnt = (rp >= 12) + (rp >= 16) + (rp >= 23) + (rp >= 32) +
                      (rp >= 46) + (rp >= 64) + (rp >= 91);
            lb = 8 + cnt;
        }
        bucket += lb;
        float s = 0.f;
        #pragma unroll
        for (int g = 0; g < 4; g++) s += rb[bucket * 16 + g * 4 + h];
        g_bias[idx] = s * 0.25f * LOG2E;      // log2 domain
    }
}

// ---------------- PTX helpers ----------------
__device__ __forceinline__ unsigned f2tf(float x) {
    unsigned r; asm("cvt.rna.tf32.f32 %0, %1;" : "=r"(r) : "f"(x)); return r;
}

#define MMA_TF32(d, a, b0, b1)                                              \
    asm volatile("mma.sync.aligned.m16n8k8.row.col.f32.tf32.tf32.f32 "      \
        "{%0,%1,%2,%3}, {%4,%5,%6,%7}, {%8,%9}, {%0,%1,%2,%3};"             \
        : "+f"(d[0]), "+f"(d[1]), "+f"(d[2]), "+f"(d[3])                    \
        : "r"(a[0]), "r"(a[1]), "r"(a[2]), "r"(a[3]), "r"(b0), "r"(b1))

#define MMA_BF16(d, a, b0, b1)                                              \
    asm volatile("mma.sync.aligned.m16n8k16.row.col.f32.bf16.bf16.f32 "     \
        "{%0,%1,%2,%3}, {%4,%5,%6,%7}, {%8,%9}, {%0,%1,%2,%3};"             \
        : "+f"(d[0]), "+f"(d[1]), "+f"(d[2]), "+f"(d[3])                    \
        : "r"(a[0]), "r"(a[1]), "r"(a[2]), "r"(a[3]), "r"(b0), "r"(b1))

__device__ __forceinline__ void ldsm4(unsigned* r, uint32_t addr) {
    asm volatile("ldmatrix.sync.aligned.m8n8.x4.shared.b16 {%0,%1,%2,%3}, [%4];"
                 : "=r"(r[0]), "=r"(r[1]), "=r"(r[2]), "=r"(r[3]) : "r"(addr));
}
__device__ __forceinline__ void ldsm2t(unsigned& r0, unsigned& r1, uint32_t addr) {
    asm volatile("ldmatrix.sync.aligned.m8n8.x2.trans.shared.b16 {%0,%1}, [%2];"
                 : "=r"(r0), "=r"(r1) : "r"(addr));
}

// pack {e0,e1} -> bf16x2 (low half = e0)
__device__ __forceinline__ unsigned pk2(float e0, float e1) {
    unsigned r; asm("cvt.rn.bf16x2.f32 %0, %1, %2;" : "=r"(r) : "f"(e1), "f"(e0)); return r;
}

__device__ __forceinline__ uint32_t s2u(const void* p) {
    uint32_t a;
    asm("{ .reg .u64 t; cvta.to.shared.u64 t, %1; cvt.u32.u64 %0, t; }" : "=r"(a) : "l"(p));
    return a;
}

// FMA-pipe exp2 (no MUFU)
__device__ __forceinline__ float exp2p(float t) {
    t = fmaxf(t, -126.f);
    float r = rintf(t);
    float f = t - r;
    int   i = (int)r;
    float p = 1.5403530e-4f;
    p = fmaf(p, f, 1.3333558e-3f);
    p = fmaf(p, f, 9.6181291e-3f);
    p = fmaf(p, f, 5.5504109e-2f);
    p = fmaf(p, f, 2.4022651e-1f);
    p = fmaf(p, f, 6.9314718e-1f);
    p = fmaf(p, f, 1.0f);
    return p * __int_as_float((i + 127) << 23);
}

#define SWZ(x) ((x) ^ (((x) >> 3) & 0x70))

// split f32x4 into bf16 hi/lo at swizzled byte offset (8B-aligned)
__device__ __forceinline__ void split_st(char* hb, char* lb, int off, float4 v) {
    unsigned h01 = pk2(v.x, v.y), h23 = pk2(v.z, v.w);
    float rx = v.x - __uint_as_float(h01 << 16);
    float ry = v.y - __uint_as_float(h01 & 0xffff0000u);
    float rz = v.z - __uint_as_float(h23 << 16);
    float rw = v.w - __uint_as_float(h23 & 0xffff0000u);
    unsigned l01 = pk2(rx, ry), l23 = pk2(rz, rw);
    int sw = SWZ(off);
    *(uint2*)(hb + sw) = make_uint2(h01, h23);
    *(uint2*)(lb + sw) = make_uint2(l01, l23);
}

// ---------------- 3xTF32 GEMM (unchanged, validated) ----------------
__global__ __launch_bounds__(256, 2)
void gemm_tf32(const float* __restrict__ A, const float* __restrict__ B,
               float* __restrict__ C,
               float* __restrict__ Qp, float* __restrict__ Kp, float* __restrict__ Vp,
               int M, int N, int K, int mode) {
    extern __shared__ float sm[];
    float* Ah = sm;
    float* Al = Ah + BM * LDT;
    float* Bh = Al + BM * LDT;
    float* Bl = Bh + BN * LDT;

    int tid  = threadIdx.x;
    int lane = tid & 31, warp = tid >> 5;
    int wm = warp >> 1, wn = warp & 1;
    int gid = lane >> 2, tig = lane & 3;
    int m0 = blockIdx.y * BM, n0 = blockIdx.x * BN;

    float acc[2][4][4];
    #pragma unroll
    for (int mi = 0; mi < 2; mi++)
        #pragma unroll
        for (int ni = 0; ni < 4; ni++)
            #pragma unroll
            for (int r = 0; r < 4; r++) acc[mi][ni][r] = 0.f;

    for (int kt = 0; kt < K; kt += BK) {
        #pragma unroll
        for (int p = 0; p < 4; p++) {
            int f = tid + p * 256;
            int row = f >> 3, seg = (f & 7) * 4;
            float4 v = *(const float4*)(A + (size_t)(m0 + row) * K + kt + seg);
            float h0 = __uint_as_float(f2tf(v.x));
            float h1 = __uint_as_float(f2tf(v.y));
            float h2 = __uint_as_float(f2tf(v.z));
            float h3 = __uint_as_float(f2tf(v.w));
            float* ah = Ah + row * LDT + seg;
            float* al = Al + row * LDT + seg;
            ah[0] = h0; ah[1] = h1; ah[2] = h2; ah[3] = h3;
            al[0] = __uint_as_float(f2tf(v.x - h0));
            al[1] = __uint_as_float(f2tf(v.y - h1));
            al[2] = __uint_as_float(f2tf(v.z - h2));
            al[3] = __uint_as_float(f2tf(v.w - h3));
        }
        #pragma unroll
        for (int p = 0; p < 2; p++) {
            int f = tid + p * 256;
            int row = f >> 3, seg = (f & 7) * 4;
            float4 v = *(const float4*)(B + (size_t)(n0 + row) * K + kt + seg);
            float h0 = __uint_as_float(f2tf(v.x));
            float h1 = __uint_as_float(f2tf(v.y));
            float h2 = __uint_as_float(f2tf(v.z));
            float h3 = __uint_as_float(f2tf(v.w));
            float* bh = Bh + row * LDT + seg;
            float* bl = Bl + row * LDT + seg;
            bh[0] = h0; bh[1] = h1; bh[2] = h2; bh[3] = h3;
            bl[0] = __uint_as_float(f2tf(v.x - h0));
            bl[1] = __uint_as_float(f2tf(v.y - h1));
            bl[2] = __uint_as_float(f2tf(v.z - h2));
            bl[3] = __uint_as_float(f2tf(v.w - h3));
        }
        __syncthreads();

        #pragma unroll
        for (int ks = 0; ks < BK / 8; ks++) {
            int k = ks * 8;
            unsigned ah[2][4], al[2][4];
            #pragma unroll
            for (int mi = 0; mi < 2; mi++) {
                int rb = wm * 32 + mi * 16;
                const float* a0 = Ah + (rb + gid) * LDT + k + tig;
                const float* a1 = Ah + (rb + gid + 8) * LDT + k + tig;
                ah[mi][0] = __float_as_uint(a0[0]);
                ah[mi][1] = __float_as_uint(a1[0]);
                ah[mi][2] = __float_as_uint(a0[4]);
                ah[mi][3] = __float_as_uint(a1[4]);
                const float* l0 = Al + (rb + gid) * LDT + k + tig;
                const float* l1 = Al + (rb + gid + 8) * LDT + k + tig;
                al[mi][0] = __float_as_uint(l0[0]);
                al[mi][1] = __float_as_uint(l1[0]);
                al[mi][2] = __float_as_uint(l0[4]);
                al[mi][3] = __float_as_uint(l1[4]);
            }
            #pragma unroll
            for (int ni = 0; ni < 4; ni++) {
                int cb = wn * 32 + ni * 8 + gid;
                unsigned bh0 = __float_as_uint(Bh[cb * LDT + k + tig]);
                unsigned bh1 = __float_as_uint(Bh[cb * LDT + k + tig + 4]);
                unsigned bl0 = __float_as_uint(Bl[cb * LDT + k + tig]);
                unsigned bl1 = __float_as_uint(Bl[cb * LDT + k + tig + 4]);
                #pragma unroll
                for (int mi = 0; mi < 2; mi++) {
                    MMA_TF32(acc[mi][ni], ah[mi], bh0, bh1);
                    MMA_TF32(acc[mi][ni], ah[mi], bl0, bl1);
                    MMA_TF32(acc[mi][ni], al[mi], bh0, bh1);
                }
            }
        }
        __syncthreads();
    }

    #pragma unroll
    for (int mi = 0; mi < 2; mi++) {
        #pragma unroll
        for (int ni = 0; ni < 4; ni++) {
            int row0 = m0 + wm * 32 + mi * 16 + gid;
            int ncol = n0 + wn * 32 + ni * 8 + tig * 2;
            float2 v01 = make_float2(acc[mi][ni][0], acc[mi][ni][1]);
            float2 v23 = make_float2(acc[mi][ni][2], acc[mi][ni][3]);
            if (mode == 0) {
                *(float2*)(C + (size_t)row0 * N + ncol)       = v01;
                *(float2*)(C + (size_t)(row0 + 8) * N + ncol) = v23;
            } else {
                int buf = ncol >> 8, rem = ncol & 255;
                float* dst = (buf == 0) ? Qp : (buf == 1) ? Kp : Vp;
                *(float2*)(dst + (size_t)row0 * DKV + rem)       = v01;
                *(float2*)(dst + (size_t)(row0 + 8) * DKV + rem) = v23;
            }
        }
    }
}

// ---------------- bf16 hi/lo mma.sync flash attention ----------------
// 256 threads = 8 warps, warp owns 16 q-rows x 64 keys. 2 CTAs/SM.
// QK^T and PV both bf16 m16n8k16 3-term hi/lo; all fragments via ldmatrix.
__global__ __launch_bounds__(256, 2)
void attn_mma() {
    extern __shared__ char smem[];
    uint32_t sb = s2u(smem);
    int tid = threadIdx.x;
    int lane = tid & 31, w = tid >> 5;
    int gid = lane >> 2, tig = lane & 3;
    int wrow = w * 16;
    int q0 = blockIdx.x * QT;
    int bh = blockIdx.y;
    int b = bh >> 2, h = bh & 3;

    // bias window: biass[i] consumed as biass[kv0 + col + 127 - row]
    float* biass = (float*)(smem + SM_BI);
    for (int i = tid; i < 2176; i += 256) {
        int t = i - 127 - q0 + 2047;
        t = max(0, min(4094, t));
        biass[i] = g_bias[t * 4 + h];
    }

    // Q tile (scaled by log2e) -> bf16 hi/lo, SW128
    const float* Qg = g_Q + ((size_t)(b * N_TOK + q0)) * DKV + h * 64;
    #pragma unroll
    for (int p = 0; p < 8; p++) {
        int f = tid + p * 256;
        int row = f >> 4, seg = (f & 15) * 4;
        float4 v = *(const float4*)(Qg + (size_t)row * DKV + seg);
        v.x *= LOG2E; v.y *= LOG2E; v.z *= LOG2E; v.w *= LOG2E;
        split_st(smem + SM_QH, smem + SM_QL, row * 128 + seg * 2, v);
    }

    // per-lane ldmatrix base offsets (bytes within tile)
    int mi = lane >> 3, r8 = lane & 7;
    int aoff = (wrow + ((mi & 1) ? 8 : 0) + r8) * 128 + ((mi & 2) ? 16 : 0);
    int boff = (((mi & 2) ? 8 : 0) + r8) * 128 + ((mi & 1) ? 16 : 0);
    int voff = (lane & 15) * 128;

    float m0r = -1e30f, m1r = -1e30f, l0r = 0.f, l1r = 0.f;
    float o[8][4];
    #pragma unroll
    for (int ni = 0; ni < 8; ni++)
        #pragma unroll
        for (int q = 0; q < 4; q++) o[ni][q] = 0.f;

    for (int kv0 = 0; kv0 < N_TOK; kv0 += KT) {
        __syncthreads();   // previous tile's reads done (also covers Q/bias on iter 0)
        const float* Kg = g_K + ((size_t)(b * N_TOK + kv0)) * DKV + h * 64;
        const float* Vg = g_V + ((size_t)(b * N_TOK + kv0)) * DKV + h * 64;
        #pragma unroll
        for (int p = 0; p < 4; p++) {
            int f = tid + p * 256;
            int row = f >> 4, seg = (f & 15) * 4;
            float4 kv = *(const float4*)(Kg + (size_t)row * DKV + seg);
            split_st(smem + SM_KH, smem + SM_KL, row * 128 + seg * 2, kv);
            float4 vv = *(const float4*)(Vg + (size_t)row * DKV + seg);
            split_st(smem + SM_VH, smem + SM_VL, row * 128 + seg * 2, vv);
        }
        __syncthreads();

        // ---- S = Q K^T ----
        float s[8][4];
        #pragma unroll
        for (int ni = 0; ni < 8; ni++)
            #pragma unroll
            for (int q = 0; q < 4; q++) s[ni][q] = 0.f;

        #pragma unroll
        for (int ks = 0; ks < 4; ks++) {
            unsigned qh[4], ql[4];
            ldsm4(qh, sb + SM_QH + SWZ(aoff + ks * 32));
            ldsm4(ql, sb + SM_QL + SWZ(aoff + ks * 32));
            #pragma unroll
            for (int np = 0; np < 4; np++) {
                unsigned kh[4], kl[4];
                int bo = boff + np * 2048 + ks * 32;
                ldsm4(kh, sb + SM_KH + SWZ(bo));
                ldsm4(kl, sb + SM_KL + SWZ(bo));
                MMA_BF16(s[2 * np],     qh, kh[0], kh[1]);
                MMA_BF16(s[2 * np],     ql, kh[0], kh[1]);
                MMA_BF16(s[2 * np],     qh, kl[0], kl[1]);
                MMA_BF16(s[2 * np + 1], qh, kh[2], kh[3]);
                MMA_BF16(s[2 * np + 1], ql, kh[2], kh[3]);
                MMA_BF16(s[2 * np + 1], qh, kl[2], kl[3]);
            }
        }

        // ---- bias add ----
        const float* bp0 = biass + (kv0 + 127 - wrow - gid);
        #pragma unroll
        for (int ni = 0; ni < 8; ni++) {
            int c = ni * 8 + 2 * tig;
            s[ni][0] += bp0[c];
            s[ni][1] += bp0[c + 1];
            s[ni][2] += bp0[c - 8];
            s[ni][3] += bp0[c - 7];
        }

        // ---- online softmax (log2 domain) ----
        float mx0 = -1e30f, mx1 = -1e30f;
        #pragma unroll
        for (int ni = 0; ni < 8; ni++) {
            mx0 = fmaxf(mx0, fmaxf(s[ni][0], s[ni][1]));
            mx1 = fmaxf(mx1, fmaxf(s[ni][2], s[ni][3]));
        }
        mx0 = fmaxf(mx0, __shfl_xor_sync(0xffffffffu, mx0, 1));
        mx0 = fmaxf(mx0, __shfl_xor_sync(0xffffffffu, mx0, 2));
        mx1 = fmaxf(mx1, __shfl_xor_sync(0xffffffffu, mx1, 1));
        mx1 = fmaxf(mx1, __shfl_xor_sync(0xffffffffu, mx1, 2));
        float mn0 = fmaxf(m0r, mx0), mn1 = fmaxf(m1r, mx1);
        float a0 = exp2p(m0r - mn0), a1 = exp2p(m1r - mn1);
        m0r = mn0; m1r = mn1;

        float ps0 = 0.f, ps1 = 0.f;
        #pragma unroll
        for (int ni = 0; ni < 8; ni++) {
            s[ni][0] = exp2p(s[ni][0] - mn0); ps0 += s[ni][0];
            s[ni][1] = exp2p(s[ni][1] - mn0); ps0 += s[ni][1];
            s[ni][2] = exp2p(s[ni][2] - mn1); ps1 += s[ni][2];
            s[ni][3] = exp2p(s[ni][3] - mn1); ps1 += s[ni][3];
        }
        ps0 += __shfl_xor_sync(0xffffffffu, ps0, 1);
        ps0 += __shfl_xor_sync(0xffffffffu, ps0, 2);
        ps1 += __shfl_xor_sync(0xffffffffu, ps1, 1);
        ps1 += __shfl_xor_sync(0xffffffffu, ps1, 2);
        l0r = l0r * a0 + ps0;
        l1r = l1r * a1 + ps1;

        #pragma unroll
        for (int ni = 0; ni < 8; ni++) {
            o[ni][0] *= a0; o[ni][1] *= a0;
            o[ni][2] *= a1; o[ni][3] *= a1;
        }

        // ---- O += P V (P in registers, bf16 hi/lo 3-term) ----
        #pragma unroll
        for (int kk = 0; kk < 4; kk++) {
            unsigned pa[4], pl[4];
            #pragma unroll
            for (int q = 0; q < 2; q++) {
                float v0 = s[2 * kk + q][0], v1 = s[2 * kk + q][1];
                float v2 = s[2 * kk + q][2], v3 = s[2 * kk + q][3];
                unsigned hp0 = pk2(v0, v1);
                unsigned hp1 = pk2(v2, v3);
                pa[2 * q + 0] = hp0;
                pa[2 * q + 1] = hp1;
                pl[2 * q + 0] = pk2(v0 - __uint_as_float(hp0 << 16),
                                    v1 - __uint_as_float(hp0 & 0xffff0000u));
                pl[2 * q + 1] = pk2(v2 - __uint_as_float(hp1 << 16),
                                    v3 - __uint_as_float(hp1 & 0xffff0000u));
            }
            #pragma unroll
            for (int ni = 0; ni < 8; ni++) {
                unsigned bh0, bh1, bl0, bl1;
                int vo = voff + kk * 2048 + ni * 16;
                ldsm2t(bh0, bh1, sb + SM_VH + SWZ(vo));
                ldsm2t(bl0, bl1, sb + SM_VL + SWZ(vo));
                MMA_BF16(o[ni], pa, bh0, bh1);
                MMA_BF16(o[ni], pl, bh0, bh1);
                MMA_BF16(o[ni], pa, bl0, bl1);
            }
        }
    }

    // epilogue
    float inv0 = 1.f / l0r, inv1 = 1.f / l1r;
    float* Og = g_O + ((size_t)(b * N_TOK + q0 + wrow + gid)) * DKV + h * 64;
    #pragma unroll
    for (int ni = 0; ni < 8; ni++) {
        int c = ni * 8 + 2 * tig;
        *(float2*)(Og + c)           = make_float2(o[ni][0] * inv0, o[ni][1] * inv0);
        *(float2*)(Og + 8 * DKV + c) = make_float2(o[ni][2] * inv1, o[ni][3] * inv1);
    }
}

// ---------------- launch ----------------
extern "C" void kernel_launch(void* const* d_in, const int* in_sizes, int n_in,
                              void* d_out, int out_size) {
    const float* hs = (const float*)d_in[0];
    const float* Wq = (const float*)d_in[1];
    const float* Wk = (const float*)d_in[2];
    const float* Wv = (const float*)d_in[3];
    const float* Wo = (const float*)d_in[4];
    const float* rb = (const float*)d_in[5];
    float* out = (float*)d_out;

    void *pWf, *pWoS, *pQ, *pK, *pV, *pO;
    cudaGetSymbolAddress(&pWf, g_Wf);
    cudaGetSymbolAddress(&pWoS, g_WoS);
    cudaGetSymbolAddress(&pQ, g_Q);
    cudaGetSymbolAddress(&pK, g_K);
    cudaGetSymbolAddress(&pV, g_V);
    cudaGetSymbolAddress(&pO, g_O);

    fold_kernel<<<1024, 256>>>(Wq, Wk, Wv, Wo, rb);

    int gsmem = (2 * BM + 2 * BN) * LDT * sizeof(float);
    cudaFuncSetAttribute(gemm_tf32, cudaFuncAttributeMaxDynamicSharedMemorySize, gsmem);
    gemm_tf32<<<dim3(768 / BN, M_TOTAL / BM), 256, gsmem>>>(
        hs, (const float*)pWf, nullptr,
        (float*)pQ, (float*)pK, (float*)pV, M_TOTAL, 768, DM, 1);

    cudaFuncSetAttribute(attn_mma, cudaFuncAttributeMaxDynamicSharedMemorySize, SM_TOT);
    attn_mma<<<dim3(N_TOK / QT, BATCH * 4), 256, SM_TOT>>>();

    gemm_tf32<<<dim3(DM / BN, M_TOTAL / BM), 256, gsmem>>>(
        (const float*)pO, (const float*)pWoS, out,
        nullptr, nullptr, nullptr, M_TOTAL, DM, DKV, 0);
}

// round 8
// speedup vs baseline: 3.3071x; 1.4303x over previous
#include <cuda_runtime.h>
#include <cuda_bf16.h>
#include <cstdint>
#include <cstddef>

#define N_TOK 2048
#define BATCH 4
#define DM    1024
#define DKV   256
#define M_TOTAL (BATCH * N_TOK)   // 8192
#define LOG2E 1.4426950408889634f

// ---- bf16 GEMM tiles (BK=64 bf16 -> 128B rows, SW128) ----
#define GBM 128
#define GBN 64
#define GBK 64
#define GSM_AH 0
#define GSM_AL 16384
#define GSM_BH 32768
#define GSM_BL 40960
#define GSM_TOT 49152

// ---- attention tiles (bf16 hi/lo, SW128, 128B rows) ----
#define QT 128
#define KT 64
#define SM_QH 0
#define SM_QL (SM_QH + 128 * 128)
#define SM_KH (SM_QL + 128 * 128)
#define SM_KL (SM_KH + 64 * 128)
#define SM_VH (SM_KL + 64 * 128)
#define SM_VL (SM_VH + 64 * 128)
#define SM_BI (SM_VL + 64 * 128)
#define SM_TOT (SM_BI + 2176 * 4)     // 74240 -> 2 CTAs/SM

// ---------------- scratch ----------------
__device__ float g_Wf[768 * 1024];
__device__ float g_WoS[1024 * 256];
__device__ float g_bias[4095 * 4];
__device__ float g_Q[M_TOTAL * DKV];
__device__ float g_O[M_TOTAL * DKV];
__device__ __nv_bfloat16 g_KH[M_TOTAL * DKV];
__device__ __nv_bfloat16 g_KL[M_TOTAL * DKV];
__device__ __nv_bfloat16 g_VH[M_TOTAL * DKV];
__device__ __nv_bfloat16 g_VL[M_TOTAL * DKV];

// ---------------- fold weights + bias table ----------------
__global__ void fold_kernel(const float* __restrict__ Wq, const float* __restrict__ Wk,
                            const float* __restrict__ Wv, const float* __restrict__ Wo,
                            const float* __restrict__ rb) {
    int idx = blockIdx.x * blockDim.x + threadIdx.x;
    if (idx < 256 * 1024) {
        int r   = idx >> 10;
        int col = idx & 1023;
        int h = r >> 6, d = r & 63;
        float sq = 0.f, sk = 0.f, sv = 0.f;
        #pragma unroll
        for (int g = 0; g < 4; g++) {
            int src = ((g * 4 + h) * 64 + d) * 1024 + col;
            sq += Wq[src]; sk += Wk[src]; sv += Wv[src];
        }
        g_Wf[(size_t)r * 1024 + col]         = sq;
        g_Wf[(size_t)(256 + r) * 1024 + col] = sk * 0.25f;
        g_Wf[(size_t)(512 + r) * 1024 + col] = sv * 0.25f;

        int j = idx >> 8;
        int c = idx & 255;
        float so = 0.f;
        #pragma unroll
        for (int g = 0; g < 4; g++) so += Wo[j * 1024 + g * 256 + c];
        g_WoS[idx] = so;
    }
    if (idx < 4095 * 4) {
        int i = idx >> 2, h = idx & 3;
        int rel = i - 2047;
        int bucket = (rel > 0) ? 16 : 0;
        int rp = rel < 0 ? -rel : rel;
        int lb;
        if (rp < 8) lb = rp;
        else {
            int cnt = (rp >= 12) + (rp >= 16) + (rp >= 23) + (rp >= 32) +
                      (rp >= 46) + (rp >= 64) + (rp >= 91);
            lb = 8 + cnt;
        }
        bucket += lb;
        float s = 0.f;
        #pragma unroll
        for (int g = 0; g < 4; g++) s += rb[bucket * 16 + g * 4 + h];
        g_bias[idx] = s * 0.25f * LOG2E;      // log2 domain
    }
}

// ---------------- PTX helpers ----------------
#define MMA_BF16(d, a, b0, b1)                                              \
    asm volatile("mma.sync.aligned.m16n8k16.row.col.f32.bf16.bf16.f32 "     \
        "{%0,%1,%2,%3}, {%4,%5,%6,%7}, {%8,%9}, {%0,%1,%2,%3};"             \
        : "+f"(d[0]), "+f"(d[1]), "+f"(d[2]), "+f"(d[3])                    \
        : "r"(a[0]), "r"(a[1]), "r"(a[2]), "r"(a[3]), "r"(b0), "r"(b1))

__device__ __forceinline__ void ldsm4(unsigned* r, uint32_t addr) {
    asm volatile("ldmatrix.sync.aligned.m8n8.x4.shared.b16 {%0,%1,%2,%3}, [%4];"
                 : "=r"(r[0]), "=r"(r[1]), "=r"(r[2]), "=r"(r[3]) : "r"(addr));
}
__device__ __forceinline__ void ldsm2t(unsigned& r0, unsigned& r1, uint32_t addr) {
    asm volatile("ldmatrix.sync.aligned.m8n8.x2.trans.shared.b16 {%0,%1}, [%2];"
                 : "=r"(r0), "=r"(r1) : "r"(addr));
}

// pack {e0,e1} -> bf16x2 (low half = e0)
__device__ __forceinline__ unsigned pk2(float e0, float e1) {
    unsigned r; asm("cvt.rn.bf16x2.f32 %0, %1, %2;" : "=r"(r) : "f"(e1), "f"(e0)); return r;
}

__device__ __forceinline__ uint32_t s2u(const void* p) {
    uint32_t a;
    asm("{ .reg .u64 t; cvta.to.shared.u64 t, %1; cvt.u32.u64 %0, t; }" : "=r"(a) : "l"(p));
    return a;
}

// FMA-pipe exp2 (no MUFU)
__device__ __forceinline__ float exp2p(float t) {
    t = fmaxf(t, -126.f);
    float r = rintf(t);
    float f = t - r;
    int   i = (int)r;
    float p = 1.5403530e-4f;
    p = fmaf(p, f, 1.3333558e-3f);
    p = fmaf(p, f, 9.6181291e-3f);
    p = fmaf(p, f, 5.5504109e-2f);
    p = fmaf(p, f, 2.4022651e-1f);
    p = fmaf(p, f, 6.9314718e-1f);
    p = fmaf(p, f, 1.0f);
    return p * __int_as_float((i + 127) << 23);
}

#define SWZ(x) ((x) ^ (((x) >> 3) & 0x70))

// split f32x4 into bf16 hi/lo at swizzled byte offset (8B-aligned)
__device__ __forceinline__ void split_st(char* hb, char* lb, int off, float4 v) {
    unsigned h01 = pk2(v.x, v.y), h23 = pk2(v.z, v.w);
    float rx = v.x - __uint_as_float(h01 << 16);
    float ry = v.y - __uint_as_float(h01 & 0xffff0000u);
    float rz = v.z - __uint_as_float(h23 << 16);
    float rw = v.w - __uint_as_float(h23 & 0xffff0000u);
    unsigned l01 = pk2(rx, ry), l23 = pk2(rz, rw);
    int sw = SWZ(off);
    *(uint2*)(hb + sw) = make_uint2(h01, h23);
    *(uint2*)(lb + sw) = make_uint2(l01, l23);
}

// store hi/lo bf16 pair to global planes
__device__ __forceinline__ void st_pair(__nv_bfloat16* H, __nv_bfloat16* L,
                                        size_t off, float a, float b) {
    unsigned hp = pk2(a, b);
    unsigned lp = pk2(a - __uint_as_float(hp << 16),
                      b - __uint_as_float(hp & 0xffff0000u));
    *(unsigned*)(H + off) = hp;
    *(unsigned*)(L + off) = lp;
}

// no-op kernel: shifts ncu's -s 5 capture onto attn_mma
__global__ void nop_kernel() {}

// ---------------- bf16 hi/lo 3-term GEMM: C[M,N] = A[M,K] * B[N,K]^T ----------------
// BM=128 BN=64 BK=64; 8 warps in 4(m)x2(n), warp tile 32x32, ldmatrix frags.
// mode 0: C f32. mode 1: QKV epilogue -> g_Q f32, K/V bf16 hi/lo planes.
__global__ __launch_bounds__(256, 2)
void gemm_bf16(const float* __restrict__ A, const float* __restrict__ B,
               float* __restrict__ C, int M, int N, int K, int mode) {
    extern __shared__ char smem[];
    uint32_t sb = s2u(smem);

    int tid  = threadIdx.x;
    int lane = tid & 31, warp = tid >> 5;
    int wm = warp >> 1, wn = warp & 1;
    int gid = lane >> 2, tig = lane & 3;
    int q8 = lane >> 3, r8 = lane & 7;
    int m0 = blockIdx.y * GBM, n0 = blockIdx.x * GBN;

    float acc[2][4][4];
    #pragma unroll
    for (int mi = 0; mi < 2; mi++)
        #pragma unroll
        for (int ni = 0; ni < 4; ni++)
            #pragma unroll
            for (int r = 0; r < 4; r++) acc[mi][ni][r] = 0.f;

    for (int kt = 0; kt < K; kt += GBK) {
        __syncthreads();
        // A tile: 128x64 f32 -> bf16 hi/lo (8 float4/thread)
        #pragma unroll
        for (int p = 0; p < 8; p++) {
            int f = tid + p * 256;
            int row = f >> 4, seg = (f & 15) * 4;
            float4 v = *(const float4*)(A + (size_t)(m0 + row) * K + kt + seg);
            split_st(smem + GSM_AH, smem + GSM_AL, row * 128 + seg * 2, v);
        }
        // B tile: 64x64 (4 float4/thread)
        #pragma unroll
        for (int p = 0; p < 4; p++) {
            int f = tid + p * 256;
            int row = f >> 4, seg = (f & 15) * 4;
            float4 v = *(const float4*)(B + (size_t)(n0 + row) * K + kt + seg);
            split_st(smem + GSM_BH, smem + GSM_BL, row * 128 + seg * 2, v);
        }
        __syncthreads();

        #pragma unroll
        for (int kb = 0; kb < 4; kb++) {
            unsigned ah[2][4], al[2][4];
            #pragma unroll
            for (int mi = 0; mi < 2; mi++) {
                int ao = (wm * 32 + mi * 16 + ((q8 & 1) ? 8 : 0) + r8) * 128
                       + ((q8 & 2) ? 16 : 0) + kb * 32;
                ldsm4(ah[mi], sb + GSM_AH + SWZ(ao));
                ldsm4(al[mi], sb + GSM_AL + SWZ(ao));
            }
            #pragma unroll
            for (int ng = 0; ng < 2; ng++) {
                unsigned bh[4], bl[4];
                int bo = (wn * 32 + ng * 16 + ((q8 & 2) ? 8 : 0) + r8) * 128
                       + ((q8 & 1) ? 16 : 0) + kb * 32;
                ldsm4(bh, sb + GSM_BH + SWZ(bo));
                ldsm4(bl, sb + GSM_BL + SWZ(bo));
                #pragma unroll
                for (int mi = 0; mi < 2; mi++) {
                    MMA_BF16(acc[mi][2 * ng],     ah[mi], bh[0], bh[1]);
                    MMA_BF16(acc[mi][2 * ng],     al[mi], bh[0], bh[1]);
                    MMA_BF16(acc[mi][2 * ng],     ah[mi], bl[0], bl[1]);
                    MMA_BF16(acc[mi][2 * ng + 1], ah[mi], bh[2], bh[3]);
                    MMA_BF16(acc[mi][2 * ng + 1], al[mi], bh[2], bh[3]);
                    MMA_BF16(acc[mi][2 * ng + 1], ah[mi], bl[2], bl[3]);
                }
            }
        }
    }

    // epilogue
    #pragma unroll
    for (int mi = 0; mi < 2; mi++) {
        #pragma unroll
        for (int ni = 0; ni < 4; ni++) {
            int row0 = m0 + wm * 32 + mi * 16 + gid;
            int ncol = n0 + wn * 32 + ni * 8 + tig * 2;
            float* a4 = acc[mi][ni];
            if (mode == 0) {
                *(float2*)(C + (size_t)row0 * N + ncol)       = make_float2(a4[0], a4[1]);
                *(float2*)(C + (size_t)(row0 + 8) * N + ncol) = make_float2(a4[2], a4[3]);
            } else {
                int buf = ncol >> 8, rem = ncol & 255;
                size_t o0 = (size_t)row0 * DKV + rem;
                size_t o1 = (size_t)(row0 + 8) * DKV + rem;
                if (buf == 0) {
                    *(float2*)(g_Q + o0) = make_float2(a4[0], a4[1]);
                    *(float2*)(g_Q + o1) = make_float2(a4[2], a4[3]);
                } else if (buf == 1) {
                    st_pair(g_KH, g_KL, o0, a4[0], a4[1]);
                    st_pair(g_KH, g_KL, o1, a4[2], a4[3]);
                } else {
                    st_pair(g_VH, g_VL, o0, a4[0], a4[1]);
                    st_pair(g_VH, g_VL, o1, a4[2], a4[3]);
                }
            }
        }
    }
}

// ---------------- bf16 hi/lo mma.sync flash attention ----------------
// 256 threads = 8 warps, warp owns 16 q-rows x 64 keys. 2 CTAs/SM.
// K/V come pre-split from global bf16 planes (pure copy + swizzle).
__global__ __launch_bounds__(256, 2)
void attn_mma() {
    extern __shared__ char smem[];
    uint32_t sb = s2u(smem);
    int tid = threadIdx.x;
    int lane = tid & 31, w = tid >> 5;
    int gid = lane >> 2, tig = lane & 3;
    int wrow = w * 16;
    int q0 = blockIdx.x * QT;
    int bh = blockIdx.y;
    int b = bh >> 2, h = bh & 3;

    // bias window
    float* biass = (float*)(smem + SM_BI);
    for (int i = tid; i < 2176; i += 256) {
        int t = i - 127 - q0 + 2047;
        t = max(0, min(4094, t));
        biass[i] = g_bias[t * 4 + h];
    }

    // Q tile (scaled by log2e) -> bf16 hi/lo
    const float* Qg = g_Q + ((size_t)(b * N_TOK + q0)) * DKV + h * 64;
    #pragma unroll
    for (int p = 0; p < 8; p++) {
        int f = tid + p * 256;
        int row = f >> 4, seg = (f & 15) * 4;
        float4 v = *(const float4*)(Qg + (size_t)row * DKV + seg);
        v.x *= LOG2E; v.y *= LOG2E; v.z *= LOG2E; v.w *= LOG2E;
        split_st(smem + SM_QH, smem + SM_QL, row * 128 + seg * 2, v);
    }

    // per-lane ldmatrix base offsets
    int mi = lane >> 3, r8 = lane & 7;
    int aoff = (wrow + ((mi & 1) ? 8 : 0) + r8) * 128 + ((mi & 2) ? 16 : 0);
    int boff = (((mi & 2) ? 8 : 0) + r8) * 128 + ((mi & 1) ? 16 : 0);
    int voff = (lane & 15) * 128;

    float m0r = -1e30f, m1r = -1e30f, l0r = 0.f, l1r = 0.f;
    float o[8][4];
    #pragma unroll
    for (int ni = 0; ni < 8; ni++)
        #pragma unroll
        for (int q = 0; q < 4; q++) o[ni][q] = 0.f;

    const __nv_bfloat16* KHg = g_KH + ((size_t)(b * N_TOK)) * DKV + h * 64;
    const __nv_bfloat16* KLg = g_KL + ((size_t)(b * N_TOK)) * DKV + h * 64;
    const __nv_bfloat16* VHg = g_VH + ((size_t)(b * N_TOK)) * DKV + h * 64;
    const __nv_bfloat16* VLg = g_VL + ((size_t)(b * N_TOK)) * DKV + h * 64;

    for (int kv0 = 0; kv0 < N_TOK; kv0 += KT) {
        __syncthreads();
        // K/V tiles: direct bf16 plane copy + swizzle (4 rows' worth per thread)
        #pragma unroll
        for (int p = 0; p < 4; p++) {
            int f = tid + p * 256;
            int row = f >> 4, seg = (f & 15) * 4;
            size_t go = (size_t)(kv0 + row) * DKV + seg;
            int so = SWZ(row * 128 + seg * 2);
            *(uint2*)(smem + SM_KH + so) = *(const uint2*)(KHg + go);
            *(uint2*)(smem + SM_KL + so) = *(const uint2*)(KLg + go);
            *(uint2*)(smem + SM_VH + so) = *(const uint2*)(VHg + go);
            *(uint2*)(smem + SM_VL + so) = *(const uint2*)(VLg + go);
        }
        __syncthreads();

        // ---- S = Q K^T (3-term hi/lo) ----
        float s[8][4];
        #pragma unroll
        for (int ni = 0; ni < 8; ni++)
            #pragma unroll
            for (int q = 0; q < 4; q++) s[ni][q] = 0.f;

        #pragma unroll
        for (int ks = 0; ks < 4; ks++) {
            unsigned qh[4], ql[4];
            ldsm4(qh, sb + SM_QH + SWZ(aoff + ks * 32));
            ldsm4(ql, sb + SM_QL + SWZ(aoff + ks * 32));
            #pragma unroll
            for (int np = 0; np < 4; np++) {
                unsigned kh[4], kl[4];
                int bo = boff + np * 2048 + ks * 32;
                ldsm4(kh, sb + SM_KH + SWZ(bo));
                ldsm4(kl, sb + SM_KL + SWZ(bo));
                MMA_BF16(s[2 * np],     qh, kh[0], kh[1]);
                MMA_BF16(s[2 * np],     ql, kh[0], kh[1]);
                MMA_BF16(s[2 * np],     qh, kl[0], kl[1]);
                MMA_BF16(s[2 * np + 1], qh, kh[2], kh[3]);
                MMA_BF16(s[2 * np + 1], ql, kh[2], kh[3]);
                MMA_BF16(s[2 * np + 1], qh, kl[2], kl[3]);
            }
        }

        // ---- bias add ----
        const float* bp0 = biass + (kv0 + 127 - wrow - gid);
        #pragma unroll
        for (int ni = 0; ni < 8; ni++) {
            int c = ni * 8 + 2 * tig;
            s[ni][0] += bp0[c];
            s[ni][1] += bp0[c + 1];
            s[ni][2] += bp0[c - 8];
            s[ni][3] += bp0[c - 7];
        }

        // ---- online softmax (log2 domain) ----
        float mx0 = -1e30f, mx1 = -1e30f;
        #pragma unroll
        for (int ni = 0; ni < 8; ni++) {
            mx0 = fmaxf(mx0, fmaxf(s[ni][0], s[ni][1]));
            mx1 = fmaxf(mx1, fmaxf(s[ni][2], s[ni][3]));
        }
        mx0 = fmaxf(mx0, __shfl_xor_sync(0xffffffffu, mx0, 1));
        mx0 = fmaxf(mx0, __shfl_xor_sync(0xffffffffu, mx0, 2));
        mx1 = fmaxf(mx1, __shfl_xor_sync(0xffffffffu, mx1, 1));
        mx1 = fmaxf(mx1, __shfl_xor_sync(0xffffffffu, mx1, 2));
        float mn0 = fmaxf(m0r, mx0), mn1 = fmaxf(m1r, mx1);
        float a0 = exp2p(m0r - mn0), a1 = exp2p(m1r - mn1);
        m0r = mn0; m1r = mn1;

        float ps0 = 0.f, ps1 = 0.f;
        #pragma unroll
        for (int ni = 0; ni < 8; ni++) {
            s[ni][0] = exp2p(s[ni][0] - mn0); ps0 += s[ni][0];
            s[ni][1] = exp2p(s[ni][1] - mn0); ps0 += s[ni][1];
            s[ni][2] = exp2p(s[ni][2] - mn1); ps1 += s[ni][2];
            s[ni][3] = exp2p(s[ni][3] - mn1); ps1 += s[ni][3];
        }
        ps0 += __shfl_xor_sync(0xffffffffu, ps0, 1);
        ps0 += __shfl_xor_sync(0xffffffffu, ps0, 2);
        ps1 += __shfl_xor_sync(0xffffffffu, ps1, 1);
        ps1 += __shfl_xor_sync(0xffffffffu, ps1, 2);
        l0r = l0r * a0 + ps0;
        l1r = l1r * a1 + ps1;

        #pragma unroll
        for (int ni = 0; ni < 8; ni++) {
            o[ni][0] *= a0; o[ni][1] *= a0;
            o[ni][2] *= a1; o[ni][3] *= a1;
        }

        // ---- O += P V (P in registers, bf16 hi/lo 3-term) ----
        #pragma unroll
        for (int kk = 0; kk < 4; kk++) {
            unsigned pa[4], pl[4];
            #pragma unroll
            for (int q = 0; q < 2; q++) {
                float v0 = s[2 * kk + q][0], v1 = s[2 * kk + q][1];
                float v2 = s[2 * kk + q][2], v3 = s[2 * kk + q][3];
                unsigned hp0 = pk2(v0, v1);
                unsigned hp1 = pk2(v2, v3);
                pa[2 * q + 0] = hp0;
                pa[2 * q + 1] = hp1;
                pl[2 * q + 0] = pk2(v0 - __uint_as_float(hp0 << 16),
                                    v1 - __uint_as_float(hp0 & 0xffff0000u));
                pl[2 * q + 1] = pk2(v2 - __uint_as_float(hp1 << 16),
                                    v3 - __uint_as_float(hp1 & 0xffff0000u));
            }
            #pragma unroll
            for (int ni = 0; ni < 8; ni++) {
                unsigned bh0, bh1, bl0, bl1;
                int vo = voff + kk * 2048 + ni * 16;
                ldsm2t(bh0, bh1, sb + SM_VH + SWZ(vo));
                ldsm2t(bl0, bl1, sb + SM_VL + SWZ(vo));
                MMA_BF16(o[ni], pa, bh0, bh1);
                MMA_BF16(o[ni], pl, bh0, bh1);
                MMA_BF16(o[ni], pa, bl0, bl1);
            }
        }
    }

    // epilogue
    float inv0 = 1.f / l0r, inv1 = 1.f / l1r;
    float* Og = g_O + ((size_t)(b * N_TOK + q0 + wrow + gid)) * DKV + h * 64;
    #pragma unroll
    for (int ni = 0; ni < 8; ni++) {
        int c = ni * 8 + 2 * tig;
        *(float2*)(Og + c)           = make_float2(o[ni][0] * inv0, o[ni][1] * inv0);
        *(float2*)(Og + 8 * DKV + c) = make_float2(o[ni][2] * inv1, o[ni][3] * inv1);
    }
}

// ---------------- launch ----------------
extern "C" void kernel_launch(void* const* d_in, const int* in_sizes, int n_in,
                              void* d_out, int out_size) {
    const float* hs = (const float*)d_in[0];
    const float* Wq = (const float*)d_in[1];
    const float* Wk = (const float*)d_in[2];
    const float* Wv = (const float*)d_in[3];
    const float* Wo = (const float*)d_in[4];
    const float* rb = (const float*)d_in[5];
    float* out = (float*)d_out;

    void *pWf, *pWoS, *pO;
    cudaGetSymbolAddress(&pWf, g_Wf);
    cudaGetSymbolAddress(&pWoS, g_WoS);
    cudaGetSymbolAddress(&pO, g_O);

    fold_kernel<<<1024, 256>>>(Wq, Wk, Wv, Wo, rb);                        // launch 0

    cudaFuncSetAttribute(gemm_bf16, cudaFuncAttributeMaxDynamicSharedMemorySize, GSM_TOT);
    // fused QKV projection: [8192,768] = hs @ Wf^T -> g_Q + K/V bf16 planes
    gemm_bf16<<<dim3(768 / GBN, M_TOTAL / GBM), 256, GSM_TOT>>>(           // launch 1
        hs, (const float*)pWf, nullptr, M_TOTAL, 768, DM, 1);

    nop_kernel<<<1, 1>>>();                                                // launch 2
    nop_kernel<<<1, 1>>>();                                                // launch 3
    nop_kernel<<<1, 1>>>();                                                // launch 4

    cudaFuncSetAttribute(attn_mma, cudaFuncAttributeMaxDynamicSharedMemorySize, SM_TOT);
    attn_mma<<<dim3(N_TOK / QT, BATCH * 4), 256, SM_TOT>>>();              // launch 5 (ncu -s 5)

    // output: [8192,1024] = O @ WoS^T
    gemm_bf16<<<dim3(DM / GBN, M_TOTAL / GBM), 256, GSM_TOT>>>(            // launch 6
        (const float*)pO, (const float*)pWoS, out, M_TOTAL, DM, DKV, 0);
}

// round 11
// speedup vs baseline: 3.5538x; 1.0746x over previous
#include <cuda_runtime.h>
#include <cuda_bf16.h>
#include <cstdint>
#include <cstddef>

#define N_TOK 2048
#define BATCH 4
#define DM    1024
#define DKV   256
#define M_TOTAL (BATCH * N_TOK)   // 8192
#define LOG2E 1.4426950408889634f

// ---- bf16 GEMM tiles (BK=64 bf16 -> 128B rows, SW128) ----
#define GBM 128
#define GBN 64
#define GBK 64
#define GSM_AH 0
#define GSM_AL 16384
#define GSM_BH 32768
#define GSM_BL 40960
#define GSM_TOT 49152

// ---- attention smem map (bf16 hi/lo planes, SW128, 128B rows) ----
#define QT 128
#define KT 64
#define KVSZ 32768                    // KH|KL|VH|VL, 8KB each
#define SM_QH 0
#define SM_QL 16384
#define SM_KV0 32768
#define SM_BI  (SM_KV0 + 2 * KVSZ)    // 98304
#define SM_TOT (SM_BI + 2176 * 4)     // 107008 -> 2 CTAs/SM (214KB < 227KB)

// ---------------- scratch ----------------
__device__ float g_Wf[768 * 1024];
__device__ float g_WoS[1024 * 256];
__device__ float g_bias[4095 * 4];
__device__ float g_O[M_TOTAL * DKV];
__device__ __nv_bfloat16 g_QH[M_TOTAL * DKV];
__device__ __nv_bfloat16 g_QL[M_TOTAL * DKV];
__device__ __nv_bfloat16 g_KH[M_TOTAL * DKV];
__device__ __nv_bfloat16 g_KL[M_TOTAL * DKV];
__device__ __nv_bfloat16 g_VH[M_TOTAL * DKV];
__device__ __nv_bfloat16 g_VL[M_TOTAL * DKV];

// ---------------- fold weights + bias table ----------------
__global__ void fold_kernel(const float* __restrict__ Wq, const float* __restrict__ Wk,
                            const float* __restrict__ Wv, const float* __restrict__ Wo,
                            const float* __restrict__ rb) {
    int idx = blockIdx.x * blockDim.x + threadIdx.x;
    if (idx < 256 * 1024) {
        int r   = idx >> 10;
        int col = idx & 1023;
        int h = r >> 6, d = r & 63;
        float sq = 0.f, sk = 0.f, sv = 0.f;
        #pragma unroll
        for (int g = 0; g < 4; g++) {
            int src = ((g * 4 + h) * 64 + d) * 1024 + col;
            sq += Wq[src]; sk += Wk[src]; sv += Wv[src];
        }
        g_Wf[(size_t)r * 1024 + col]         = sq * LOG2E;   // fold log2e into Q
        g_Wf[(size_t)(256 + r) * 1024 + col] = sk * 0.25f;
        g_Wf[(size_t)(512 + r) * 1024 + col] = sv * 0.25f;

        int j = idx >> 8;
        int c = idx & 255;
        float so = 0.f;
        #pragma unroll
        for (int g = 0; g < 4; g++) so += Wo[j * 1024 + g * 256 + c];
        g_WoS[idx] = so;
    }
    if (idx < 4095 * 4) {
        int i = idx >> 2, h = idx & 3;
        int rel = i - 2047;
        int bucket = (rel > 0) ? 16 : 0;
        int rp = rel < 0 ? -rel : rel;
        int lb;
        if (rp < 8) lb = rp;
        else {
            int cnt = (rp >= 12) + (rp >= 16) + (rp >= 23) + (rp >= 32) +
                      (rp >= 46) + (rp >= 64) + (rp >= 91);
            lb = 8 + cnt;
        }
        bucket += lb;
        float s = 0.f;
        #pragma unroll
        for (int g = 0; g < 4; g++) s += rb[bucket * 16 + g * 4 + h];
        g_bias[idx] = s * 0.25f * LOG2E;      // log2 domain
    }
}

// ---------------- PTX helpers ----------------
#define MMA_BF16(d, a, b0, b1)                                              \
    asm volatile("mma.sync.aligned.m16n8k16.row.col.f32.bf16.bf16.f32 "     \
        "{%0,%1,%2,%3}, {%4,%5,%6,%7}, {%8,%9}, {%0,%1,%2,%3};"             \
        : "+f"(d[0]), "+f"(d[1]), "+f"(d[2]), "+f"(d[3])                    \
        : "r"(a[0]), "r"(a[1]), "r"(a[2]), "r"(a[3]), "r"(b0), "r"(b1))

__device__ __forceinline__ void ldsm4(unsigned* r, uint32_t addr) {
    asm volatile("ldmatrix.sync.aligned.m8n8.x4.shared.b16 {%0,%1,%2,%3}, [%4];"
                 : "=r"(r[0]), "=r"(r[1]), "=r"(r[2]), "=r"(r[3]) : "r"(addr));
}
__device__ __forceinline__ void ldsm2t(unsigned& r0, unsigned& r1, uint32_t addr) {
    asm volatile("ldmatrix.sync.aligned.m8n8.x2.trans.shared.b16 {%0,%1}, [%2];"
                 : "=r"(r0), "=r"(r1) : "r"(addr));
}

__device__ __forceinline__ unsigned pk2(float e0, float e1) {
    unsigned r; asm("cvt.rn.bf16x2.f32 %0, %1, %2;" : "=r"(r) : "f"(e1), "f"(e0)); return r;
}

__device__ __forceinline__ uint32_t s2u(const void* p) {
    uint32_t a;
    asm("{ .reg .u64 t; cvta.to.shared.u64 t, %1; cvt.u32.u64 %0, t; }" : "=r"(a) : "l"(p));
    return a;
}

__device__ __forceinline__ void cpa16(uint32_t dst, const void* src) {
    asm volatile("cp.async.cg.shared.global [%0], [%1], 16;" :: "r"(dst), "l"(src));
}
#define CP_COMMIT() asm volatile("cp.async.commit_group;" ::: "memory")
#define CP_WAIT0()  asm volatile("cp.async.wait_group 0;" ::: "memory")

// FMA-pipe exp2 (no MUFU)
__device__ __forceinline__ float exp2p(float t) {
    t = fmaxf(t, -126.f);
    float r = rintf(t);
    float f = t - r;
    int   i = (int)r;
    float p = 1.5403530e-4f;
    p = fmaf(p, f, 1.3333558e-3f);
    p = fmaf(p, f, 9.6181291e-3f);
    p = fmaf(p, f, 5.5504109e-2f);
    p = fmaf(p, f, 2.4022651e-1f);
    p = fmaf(p, f, 6.9314718e-1f);
    p = fmaf(p, f, 1.0f);
    return p * __int_as_float((i + 127) << 23);
}

#define SWZ(x) ((x) ^ (((x) >> 3) & 0x70))

// split f32x4 into bf16 hi/lo at swizzled byte offset
__device__ __forceinline__ void split_st(char* hb, char* lb, int off, float4 v) {
    unsigned h01 = pk2(v.x, v.y), h23 = pk2(v.z, v.w);
    float rx = v.x - __uint_as_float(h01 << 16);
    float ry = v.y - __uint_as_float(h01 & 0xffff0000u);
    float rz = v.z - __uint_as_float(h23 << 16);
    float rw = v.w - __uint_as_float(h23 & 0xffff0000u);
    unsigned l01 = pk2(rx, ry), l23 = pk2(rz, rw);
    int sw = SWZ(off);
    *(uint2*)(hb + sw) = make_uint2(h01, h23);
    *(uint2*)(lb + sw) = make_uint2(l01, l23);
}

__device__ __forceinline__ void st_pair(__nv_bfloat16* H, __nv_bfloat16* L,
                                        size_t off, float a, float b) {
    unsigned hp = pk2(a, b);
    unsigned lp = pk2(a - __uint_as_float(hp << 16),
                      b - __uint_as_float(hp & 0xffff0000u));
    *(unsigned*)(H + off) = hp;
    *(unsigned*)(L + off) = lp;
}

// ---------------- bf16 hi/lo 3-term GEMM ----------------
// mode 0: C f32. mode 1: QKV epilogue -> Q/K/V bf16 hi/lo planes.
__global__ __launch_bounds__(256, 2)
void gemm_bf16(const float* __restrict__ A, const float* __restrict__ B,
               float* __restrict__ C, int M, int N, int K, int mode) {
    extern __shared__ char smem[];
    uint32_t sb = s2u(smem);

    int tid  = threadIdx.x;
    int lane = tid & 31, warp = tid >> 5;
    int wm = warp >> 1, wn = warp & 1;
    int gid = lane >> 2, tig = lane & 3;
    int q8 = lane >> 3, r8 = lane & 7;
    int m0 = blockIdx.y * GBM, n0 = blockIdx.x * GBN;

    float acc[2][4][4];
    #pragma unroll
    for (int mi = 0; mi < 2; mi++)
        #pragma unroll
        for (int ni = 0; ni < 4; ni++)
            #pragma unroll
            for (int r = 0; r < 4; r++) acc[mi][ni][r] = 0.f;

    for (int kt = 0; kt < K; kt += GBK) {
        __syncthreads();
        #pragma unroll
        for (int p = 0; p < 8; p++) {
            int f = tid + p * 256;
            int row = f >> 4, seg = (f & 15) * 4;
            float4 v = *(const float4*)(A + (size_t)(m0 + row) * K + kt + seg);
            split_st(smem + GSM_AH, smem + GSM_AL, row * 128 + seg * 2, v);
        }
        #pragma unroll
        for (int p = 0; p < 4; p++) {
            int f = tid + p * 256;
            int row = f >> 4, seg = (f & 15) * 4;
            float4 v = *(const float4*)(B + (size_t)(n0 + row) * K + kt + seg);
            split_st(smem + GSM_BH, smem + GSM_BL, row * 128 + seg * 2, v);
        }
        __syncthreads();

        #pragma unroll
        for (int kb = 0; kb < 4; kb++) {
            unsigned ah[2][4], al[2][4];
            #pragma unroll
            for (int mi = 0; mi < 2; mi++) {
                int ao = (wm * 32 + mi * 16 + ((q8 & 1) ? 8 : 0) + r8) * 128
                       + ((q8 & 2) ? 16 : 0) + kb * 32;
                ldsm4(ah[mi], sb + GSM_AH + SWZ(ao));
                ldsm4(al[mi], sb + GSM_AL + SWZ(ao));
            }
            #pragma unroll
            for (int ng = 0; ng < 2; ng++) {
                unsigned bh[4], bl[4];
                int bo = (wn * 32 + ng * 16 + ((q8 & 2) ? 8 : 0) + r8) * 128
                       + ((q8 & 1) ? 16 : 0) + kb * 32;
                ldsm4(bh, sb + GSM_BH + SWZ(bo));
                ldsm4(bl, sb + GSM_BL + SWZ(bo));
                #pragma unroll
                for (int mi = 0; mi < 2; mi++) {
                    MMA_BF16(acc[mi][2 * ng],     ah[mi], bh[0], bh[1]);
                    MMA_BF16(acc[mi][2 * ng],     al[mi], bh[0], bh[1]);
                    MMA_BF16(acc[mi][2 * ng],     ah[mi], bl[0], bl[1]);
                    MMA_BF16(acc[mi][2 * ng + 1], ah[mi], bh[2], bh[3]);
                    MMA_BF16(acc[mi][2 * ng + 1], al[mi], bh[2], bh[3]);
                    MMA_BF16(acc[mi][2 * ng + 1], ah[mi], bl[2], bl[3]);
                }
            }
        }
    }

    #pragma unroll
    for (int mi = 0; mi < 2; mi++) {
        #pragma unroll
        for (int ni = 0; ni < 4; ni++) {
            int row0 = m0 + wm * 32 + mi * 16 + gid;
            int ncol = n0 + wn * 32 + ni * 8 + tig * 2;
            float* a4 = acc[mi][ni];
            if (mode == 0) {
                *(float2*)(C + (size_t)row0 * N + ncol)       = make_float2(a4[0], a4[1]);
                *(float2*)(C + (size_t)(row0 + 8) * N + ncol) = make_float2(a4[2], a4[3]);
            } else {
                int buf = ncol >> 8, rem = ncol & 255;
                size_t o0 = (size_t)row0 * DKV + rem;
                size_t o1 = (size_t)(row0 + 8) * DKV + rem;
                if (buf == 0) {
                    st_pair(g_QH, g_QL, o0, a4[0], a4[1]);
                    st_pair(g_QH, g_QL, o1, a4[2], a4[3]);
                } else if (buf == 1) {
                    st_pair(g_KH, g_KL, o0, a4[0], a4[1]);
                    st_pair(g_KH, g_KL, o1, a4[2], a4[3]);
                } else {
                    st_pair(g_VH, g_VL, o0, a4[0], a4[1]);
                    st_pair(g_VH, g_VL, o1, a4[2], a4[3]);
                }
            }
        }
    }
}

// ---------------- KV tile prefetch (cp.async, 16B chunks) ----------------
__device__ __forceinline__ void prefetch_kv(
    uint32_t kvb, const __nv_bfloat16* KH, const __nv_bfloat16* KL,
    const __nv_bfloat16* VH, const __nv_bfloat16* VL, int kv0, int tid) {
    #pragma unroll
    for (int p = 0; p < 2; p++) {
        int f = tid + p * 256;            // 0..511 chunks (64 rows x 8)
        int row = f >> 3, c8 = f & 7;
        size_t go = (size_t)(kv0 + row) * DKV + c8 * 8;
        int so = SWZ(row * 128 + c8 * 16);
        cpa16(kvb + so,         KH + go);
        cpa16(kvb + 8192 + so,  KL + go);
        cpa16(kvb + 16384 + so, VH + go);
        cpa16(kvb + 24576 + so, VL + go);
    }
}

// ---------------- bf16 hi/lo mma.sync flash attention, cp.async pipelined ----------------
__global__ __launch_bounds__(256, 2)
void attn_mma() {
    extern __shared__ char smem[];
    uint32_t sb = s2u(smem);
    int tid = threadIdx.x;
    int lane = tid & 31, w = tid >> 5;
    int gid = lane >> 2, tig = lane & 3;
    int wrow = w * 16;
    int q0 = blockIdx.x * QT;
    int bh = blockIdx.y;
    int b = bh >> 2, h = bh & 3;

    // bias window (regular STS; covered by loop-top sync)
    float* biass = (float*)(smem + SM_BI);
    for (int i = tid; i < 2176; i += 256) {
        int t = i - 127 - q0 + 2047;
        t = max(0, min(4094, t));
        biass[i] = g_bias[t * 4 + h];
    }

    size_t base = (size_t)(b * N_TOK) * DKV + h * 64;
    const __nv_bfloat16* QHg = g_QH + base + (size_t)q0 * DKV;
    const __nv_bfloat16* QLg = g_QL + base + (size_t)q0 * DKV;
    const __nv_bfloat16* KHg = g_KH + base;
    const __nv_bfloat16* KLg = g_KL + base;
    const __nv_bfloat16* VHg = g_VH + base;
    const __nv_bfloat16* VLg = g_VL + base;

    // Q planes via cp.async (128 rows x 8 chunks = 1024)
    #pragma unroll
    for (int p = 0; p < 4; p++) {
        int f = tid + p * 256;
        int row = f >> 3, c8 = f & 7;
        size_t go = (size_t)row * DKV + c8 * 8;
        int so = SWZ(row * 128 + c8 * 16);
        cpa16(sb + SM_QH + so, QHg + go);
        cpa16(sb + SM_QL + so, QLg + go);
    }
    prefetch_kv(sb + SM_KV0, KHg, KLg, VHg, VLg, 0, tid);
    CP_COMMIT();

    // per-lane ldmatrix base offsets
    int mi = lane >> 3, r8 = lane & 7;
    int aoff = (wrow + ((mi & 1) ? 8 : 0) + r8) * 128 + ((mi & 2) ? 16 : 0);
    int boff = (((mi & 2) ? 8 : 0) + r8) * 128 + ((mi & 1) ? 16 : 0);
    int voff = (lane & 15) * 128;

    float m0r = -1e30f, m1r = -1e30f, l0r = 0.f, l1r = 0.f;
    float o[8][4];
    #pragma unroll
    for (int ni = 0; ni < 8; ni++)
        #pragma unroll
        for (int q = 0; q < 4; q++) o[ni][q] = 0.f;

    for (int kv0 = 0, t = 0; kv0 < N_TOK; kv0 += KT, t++) {
        CP_WAIT0();
        __syncthreads();
        if (kv0 + KT < N_TOK) {
            prefetch_kv(sb + SM_KV0 + ((t + 1) & 1) * KVSZ,
                        KHg, KLg, VHg, VLg, kv0 + KT, tid);
            CP_COMMIT();
        }
        uint32_t kvb = sb + SM_KV0 + (t & 1) * KVSZ;

        // ---- S = Q K^T (3-term hi/lo) ----
        float s[8][4];
        #pragma unroll
        for (int ni = 0; ni < 8; ni++)
            #pragma unroll
            for (int q = 0; q < 4; q++) s[ni][q] = 0.f;

        #pragma unroll
        for (int ks = 0; ks < 4; ks++) {
            unsigned qh[4], ql[4];
            ldsm4(qh, sb + SM_QH + SWZ(aoff + ks * 32));
            ldsm4(ql, sb + SM_QL + SWZ(aoff + ks * 32));
            #pragma unroll
            for (int np = 0; np < 4; np++) {
                unsigned kh[4], kl[4];
                int bo = boff + np * 2048 + ks * 32;
                ldsm4(kh, kvb + SWZ(bo));
                ldsm4(kl, kvb + 8192 + SWZ(bo));
                MMA_BF16(s[2 * np],     qh, kh[0], kh[1]);
                MMA_BF16(s[2 * np],     ql, kh[0], kh[1]);
                MMA_BF16(s[2 * np],     qh, kl[0], kl[1]);
                MMA_BF16(s[2 * np + 1], qh, kh[2], kh[3]);
                MMA_BF16(s[2 * np + 1], ql, kh[2], kh[3]);
                MMA_BF16(s[2 * np + 1], qh, kl[2], kl[3]);
            }
        }

        // ---- bias add ----
        const float* bp0 = biass + (kv0 + 127 - wrow - gid);
        #pragma unroll
        for (int ni = 0; ni < 8; ni++) {
            int c = ni * 8 + 2 * tig;
            s[ni][0] += bp0[c];
            s[ni][1] += bp0[c + 1];
            s[ni][2] += bp0[c - 8];
            s[ni][3] += bp0[c - 7];
        }

        // ---- online softmax (log2 domain) ----
        float mx0 = -1e30f, mx1 = -1e30f;
        #pragma unroll
        for (int ni = 0; ni < 8; ni++) {
            mx0 = fmaxf(mx0, fmaxf(s[ni][0], s[ni][1]));
            mx1 = fmaxf(mx1, fmaxf(s[ni][2], s[ni][3]));
        }
        mx0 = fmaxf(mx0, __shfl_xor_sync(0xffffffffu, mx0, 1));
        mx0 = fmaxf(mx0, __shfl_xor_sync(0xffffffffu, mx0, 2));
        mx1 = fmaxf(mx1, __shfl_xor_sync(0xffffffffu, mx1, 1));
        mx1 = fmaxf(mx1, __shfl_xor_sync(0xffffffffu, mx1, 2));
        float mn0 = fmaxf(m0r, mx0), mn1 = fmaxf(m1r, mx1);
        float a0 = exp2p(m0r - mn0), a1 = exp2p(m1r - mn1);
        m0r = mn0; m1r = mn1;

        float ps0 = 0.f, ps1 = 0.f;
        #pragma unroll
        for (int ni = 0; ni < 8; ni++) {
            s[ni][0] = exp2p(s[ni][0] - mn0); ps0 += s[ni][0];
            s[ni][1] = exp2p(s[ni][1] - mn0); ps0 += s[ni][1];
            s[ni][2] = exp2p(s[ni][2] - mn1); ps1 += s[ni][2];
            s[ni][3] = exp2p(s[ni][3] - mn1); ps1 += s[ni][3];
        }
        ps0 += __shfl_xor_sync(0xffffffffu, ps0, 1);
        ps0 += __shfl_xor_sync(0xffffffffu, ps0, 2);
        ps1 += __shfl_xor_sync(0xffffffffu, ps1, 1);
        ps1 += __shfl_xor_sync(0xffffffffu, ps1, 2);
        l0r = l0r * a0 + ps0;
        l1r = l1r * a1 + ps1;

        #pragma unroll
        for (int ni = 0; ni < 8; ni++) {
            o[ni][0] *= a0; o[ni][1] *= a0;
            o[ni][2] *= a1; o[ni][3] *= a1;
        }

        // ---- O += P V (P in registers, bf16 hi/lo 3-term) ----
        #pragma unroll
        for (int kk = 0; kk < 4; kk++) {
            unsigned pa[4], pl[4];
            #pragma unroll
            for (int q = 0; q < 2; q++) {
                float v0 = s[2 * kk + q][0], v1 = s[2 * kk + q][1];
                float v2 = s[2 * kk + q][2], v3 = s[2 * kk + q][3];
                unsigned hp0 = pk2(v0, v1);
                unsigned hp1 = pk2(v2, v3);
                pa[2 * q + 0] = hp0;
                pa[2 * q + 1] = hp1;
                pl[2 * q + 0] = pk2(v0 - __uint_as_float(hp0 << 16),
                                    v1 - __uint_as_float(hp0 & 0xffff0000u));
                pl[2 * q + 1] = pk2(v2 - __uint_as_float(hp1 << 16),
                                    v3 - __uint_as_float(hp1 & 0xffff0000u));
            }
            #pragma unroll
            for (int ni = 0; ni < 8; ni++) {
                unsigned bh0, bh1, bl0, bl1;
                int vo = voff + kk * 2048 + ni * 16;
                ldsm2t(bh0, bh1, kvb + 16384 + SWZ(vo));
                ldsm2t(bl0, bl1, kvb + 24576 + SWZ(vo));
                MMA_BF16(o[ni], pa, bh0, bh1);
                MMA_BF16(o[ni], pl, bh0, bh1);
                MMA_BF16(o[ni], pa, bl0, bl1);
            }
        }
    }

    // epilogue
    float inv0 = 1.f / l0r, inv1 = 1.f / l1r;
    float* Og = g_O + ((size_t)(b * N_TOK + q0 + wrow + gid)) * DKV + h * 64;
    #pragma unroll
    for (int ni = 0; ni < 8; ni++) {
        int c = ni * 8 + 2 * tig;
        *(float2*)(Og + c)           = make_float2(o[ni][0] * inv0, o[ni][1] * inv0);
        *(float2*)(Og + 8 * DKV + c) = make_float2(o[ni][2] * inv1, o[ni][3] * inv1);
    }
}

// ---------------- launch ----------------
extern "C" void kernel_launch(void* const* d_in, const int* in_sizes, int n_in,
                              void* d_out, int out_size) {
    const float* hs = (const float*)d_in[0];
    const float* Wq = (const float*)d_in[1];
    const float* Wk = (const float*)d_in[2];
    const float* Wv = (const float*)d_in[3];
    const float* Wo = (const float*)d_in[4];
    const float* rb = (const float*)d_in[5];
    float* out = (float*)d_out;

    void *pWf, *pWoS, *pO;
    cudaGetSymbolAddress(&pWf, g_Wf);
    cudaGetSymbolAddress(&pWoS, g_WoS);
    cudaGetSymbolAddress(&pO, g_O);

    fold_kernel<<<1024, 256>>>(Wq, Wk, Wv, Wo, rb);

    cudaFuncSetAttribute(gemm_bf16, cudaFuncAttributeMaxDynamicSharedMemorySize, GSM_TOT);
    gemm_bf16<<<dim3(768 / GBN, M_TOTAL / GBM), 256, GSM_TOT>>>(
        hs, (const float*)pWf, nullptr, M_TOTAL, 768, DM, 1);

    cudaFuncSetAttribute(attn_mma, cudaFuncAttributeMaxDynamicSharedMemorySize, SM_TOT);
    attn_mma<<<dim3(N_TOK / QT, BATCH * 4), 256, SM_TOT>>>();

    gemm_bf16<<<dim3(DM / GBN, M_TOTAL / GBM), 256, GSM_TOT>>>(
        (const float*)pO, (const float*)pWoS, out, M_TOTAL, DM, DKV, 0);
}